// round 2
// baseline (speedup 1.0000x reference)
#include <cuda_runtime.h>
#include <math.h>

// Problem constants
#define T_SEQ 4096
#define C_DIM 768
#define NHEAD 12
#define HDIM  64
#define QKV_LD (3 * C_DIM)

// Scratch (allocation-guard-safe device globals)
__device__ float g_qkv[(size_t)T_SEQ * 3 * C_DIM];  // [T, 3C]: Q|K|V concatenated
__device__ float g_y[(size_t)T_SEQ * C_DIM];        // attention output [T, C]

// ---------------------------------------------------------------------------
// Classic 128x128x8 fp32 GEMM with bias: C[M,N] = A[M,K] @ B[K,N] + bias[N]
// 256 threads, 8x8 register tile per thread. Requires M%128==0, N%128==0, K%8==0.
// ---------------------------------------------------------------------------
__global__ __launch_bounds__(256) void sgemm_bias(
    const float* __restrict__ A, const float* __restrict__ B,
    const float* __restrict__ bias, float* __restrict__ Cmat,
    int M, int N, int K)
{
    __shared__ float As[8][128];   // A transposed: As[k][m]
    __shared__ float Bs[8][128];   // Bs[k][n]

    const int tid = threadIdx.x;
    const int tx = tid & 15;       // N-direction (8 cols each)
    const int ty = tid >> 4;       // M-direction (8 rows each)
    const int bx = blockIdx.x;     // N tile
    const int by = blockIdx.y;     // M tile

    float acc[8][8];
#pragma unroll
    for (int i = 0; i < 8; i++)
#pragma unroll
        for (int j = 0; j < 8; j++) acc[i][j] = 0.0f;

    const int aRow = tid >> 1;          // 0..127
    const int aCol = (tid & 1) * 4;     // 0 or 4
    const int bRow = tid >> 5;          // 0..7
    const int bCol = (tid & 31) * 4;    // 0..124

    const float* Ag = A + (size_t)(by * 128) * K;
    const float* Bg = B + (size_t)(bx * 128);

    for (int k0 = 0; k0 < K; k0 += 8) {
        float4 a4 = *reinterpret_cast<const float4*>(Ag + (size_t)aRow * K + k0 + aCol);
        As[aCol + 0][aRow] = a4.x;
        As[aCol + 1][aRow] = a4.y;
        As[aCol + 2][aRow] = a4.z;
        As[aCol + 3][aRow] = a4.w;
        float4 b4 = *reinterpret_cast<const float4*>(Bg + (size_t)(k0 + bRow) * N + bCol);
        *reinterpret_cast<float4*>(&Bs[bRow][bCol]) = b4;
        __syncthreads();

#pragma unroll
        for (int kk = 0; kk < 8; kk++) {
            float ar[8], br[8];
            *reinterpret_cast<float4*>(&ar[0]) = *reinterpret_cast<float4*>(&As[kk][ty * 8]);
            *reinterpret_cast<float4*>(&ar[4]) = *reinterpret_cast<float4*>(&As[kk][ty * 8 + 4]);
            *reinterpret_cast<float4*>(&br[0]) = *reinterpret_cast<float4*>(&Bs[kk][tx * 8]);
            *reinterpret_cast<float4*>(&br[4]) = *reinterpret_cast<float4*>(&Bs[kk][tx * 8 + 4]);
#pragma unroll
            for (int i = 0; i < 8; i++)
#pragma unroll
                for (int j = 0; j < 8; j++)
                    acc[i][j] = fmaf(ar[i], br[j], acc[i][j]);
        }
        __syncthreads();
    }

#pragma unroll
    for (int i = 0; i < 8; i++) {
        const int row = by * 128 + ty * 8 + i;
#pragma unroll
        for (int j = 0; j < 8; j += 4) {
            const int col = bx * 128 + tx * 8 + j;
            float4 o;
            o.x = acc[i][j + 0] + bias[col + 0];
            o.y = acc[i][j + 1] + bias[col + 1];
            o.z = acc[i][j + 2] + bias[col + 2];
            o.w = acc[i][j + 3] + bias[col + 3];
            *reinterpret_cast<float4*>(Cmat + (size_t)row * N + col) = o;
        }
    }
}

// ---------------------------------------------------------------------------
// Flash-style causal attention, fp32, online softmax.
// Grid: (T/64 query blocks, NHEAD). 256 threads; each owns a 4x4 tile.
// SMEM: Qt[d][row], KP[.][.] (K^T then reused for P), Vs[key][dim] = 48 KB.
// ---------------------------------------------------------------------------
__global__ __launch_bounds__(256) void attn_kernel(
    const float* __restrict__ qkv, float* __restrict__ y)
{
    __shared__ float Qt[64][64];  // Qt[d][row], pre-scaled by 1/sqrt(D)
    __shared__ float KP[64][64];  // phase 1: K^T[d][key]; phase 2: P[row][key]
    __shared__ float Vs[64][64];  // Vs[key][dim]

    const int qb = (int)gridDim.x - 1 - (int)blockIdx.x;  // longest CTAs first
    const int h  = blockIdx.y;
    const int tid = threadIdx.x;
    const int tx = tid & 15;      // key / dim direction (4 each)
    const int ty = tid >> 4;      // query row direction (4 each)

    const float* Qg = qkv + h * HDIM;
    const float* Kg = qkv + C_DIM + h * HDIM;
    const float* Vg = qkv + 2 * C_DIM + h * HDIM;
    const float scale = 0.125f;   // 1/sqrt(64)

    // Load Q block transposed + pre-scaled
    for (int i = tid; i < 64 * 16; i += 256) {
        const int row = i >> 4;
        const int c4  = (i & 15) << 2;
        float4 q4 = *reinterpret_cast<const float4*>(
            Qg + (size_t)(qb * 64 + row) * QKV_LD + c4);
        Qt[c4 + 0][row] = q4.x * scale;
        Qt[c4 + 1][row] = q4.y * scale;
        Qt[c4 + 2][row] = q4.z * scale;
        Qt[c4 + 3][row] = q4.w * scale;
    }

    float o[4][4];
#pragma unroll
    for (int r = 0; r < 4; r++)
#pragma unroll
        for (int c = 0; c < 4; c++) o[r][c] = 0.0f;
    float m[4], l[4];
#pragma unroll
    for (int r = 0; r < 4; r++) { m[r] = -INFINITY; l[r] = 0.0f; }

    for (int kb = 0; kb <= qb; kb++) {
        __syncthreads();  // Q ready (kb=0) / previous PV done reading KP,Vs
        // Load K transposed and V natural
        for (int i = tid; i < 64 * 16; i += 256) {
            const int row = i >> 4;
            const int c4  = (i & 15) << 2;
            float4 k4 = *reinterpret_cast<const float4*>(
                Kg + (size_t)(kb * 64 + row) * QKV_LD + c4);
            KP[c4 + 0][row] = k4.x;
            KP[c4 + 1][row] = k4.y;
            KP[c4 + 2][row] = k4.z;
            KP[c4 + 3][row] = k4.w;
            float4 v4 = *reinterpret_cast<const float4*>(
                Vg + (size_t)(kb * 64 + row) * QKV_LD + c4);
            *reinterpret_cast<float4*>(&Vs[row][c4]) = v4;
        }
        __syncthreads();

        // S = (Q*scale) @ K^T  — 4x4 tile per thread
        float s[4][4];
#pragma unroll
        for (int r = 0; r < 4; r++)
#pragma unroll
            for (int c = 0; c < 4; c++) s[r][c] = 0.0f;
#pragma unroll 8
        for (int d = 0; d < 64; d++) {
            float4 q4 = *reinterpret_cast<float4*>(&Qt[d][ty << 2]);
            float4 k4 = *reinterpret_cast<float4*>(&KP[d][tx << 2]);
            s[0][0] = fmaf(q4.x, k4.x, s[0][0]); s[0][1] = fmaf(q4.x, k4.y, s[0][1]);
            s[0][2] = fmaf(q4.x, k4.z, s[0][2]); s[0][3] = fmaf(q4.x, k4.w, s[0][3]);
            s[1][0] = fmaf(q4.y, k4.x, s[1][0]); s[1][1] = fmaf(q4.y, k4.y, s[1][1]);
            s[1][2] = fmaf(q4.y, k4.z, s[1][2]); s[1][3] = fmaf(q4.y, k4.w, s[1][3]);
            s[2][0] = fmaf(q4.z, k4.x, s[2][0]); s[2][1] = fmaf(q4.z, k4.y, s[2][1]);
            s[2][2] = fmaf(q4.z, k4.z, s[2][2]); s[2][3] = fmaf(q4.z, k4.w, s[2][3]);
            s[3][0] = fmaf(q4.w, k4.x, s[3][0]); s[3][1] = fmaf(q4.w, k4.y, s[3][1]);
            s[3][2] = fmaf(q4.w, k4.z, s[3][2]); s[3][3] = fmaf(q4.w, k4.w, s[3][3]);
        }

        // Causal mask on the diagonal block only
        if (kb == qb) {
#pragma unroll
            for (int r = 0; r < 4; r++)
#pragma unroll
                for (int c = 0; c < 4; c++)
                    if ((tx << 2) + c > (ty << 2) + r) s[r][c] = -1e30f;
        }
        __syncthreads();  // all reads of KP (as K^T) finished

        // Online softmax (row stats shuffle-reduced over the 16-lane tx group)
        float pr[4][4], corr[4];
#pragma unroll
        for (int r = 0; r < 4; r++) {
            float mx = fmaxf(fmaxf(s[r][0], s[r][1]), fmaxf(s[r][2], s[r][3]));
#pragma unroll
            for (int off = 8; off >= 1; off >>= 1)
                mx = fmaxf(mx, __shfl_xor_sync(0xffffffffu, mx, off));
            const float mn = fmaxf(m[r], mx);
            corr[r] = __expf(m[r] - mn);
            float rs = 0.0f;
#pragma unroll
            for (int c = 0; c < 4; c++) {
                pr[r][c] = __expf(s[r][c] - mn);
                rs += pr[r][c];
            }
#pragma unroll
            for (int off = 8; off >= 1; off >>= 1)
                rs += __shfl_xor_sync(0xffffffffu, rs, off);
            l[r] = l[r] * corr[r] + rs;
            m[r] = mn;
        }
#pragma unroll
        for (int r = 0; r < 4; r++)
#pragma unroll
            for (int c = 0; c < 4; c++) o[r][c] *= corr[r];

        // Write P into the K buffer (row-major), float4 per row
#pragma unroll
        for (int r = 0; r < 4; r++) {
            float4 p4 = make_float4(pr[r][0], pr[r][1], pr[r][2], pr[r][3]);
            *reinterpret_cast<float4*>(&KP[(ty << 2) + r][tx << 2]) = p4;
        }
        __syncthreads();

        // O += P @ V
#pragma unroll 4
        for (int k = 0; k < 64; k += 4) {
            float4 v0 = *reinterpret_cast<float4*>(&Vs[k + 0][tx << 2]);
            float4 v1 = *reinterpret_cast<float4*>(&Vs[k + 1][tx << 2]);
            float4 v2 = *reinterpret_cast<float4*>(&Vs[k + 2][tx << 2]);
            float4 v3 = *reinterpret_cast<float4*>(&Vs[k + 3][tx << 2]);
#pragma unroll
            for (int r = 0; r < 4; r++) {
                float4 p4 = *reinterpret_cast<float4*>(&KP[(ty << 2) + r][k]);
                o[r][0] = fmaf(p4.x, v0.x, fmaf(p4.y, v1.x, fmaf(p4.z, v2.x, fmaf(p4.w, v3.x, o[r][0]))));
                o[r][1] = fmaf(p4.x, v0.y, fmaf(p4.y, v1.y, fmaf(p4.z, v2.y, fmaf(p4.w, v3.y, o[r][1]))));
                o[r][2] = fmaf(p4.x, v0.z, fmaf(p4.y, v1.z, fmaf(p4.z, v2.z, fmaf(p4.w, v3.z, o[r][2]))));
                o[r][3] = fmaf(p4.x, v0.w, fmaf(p4.y, v1.w, fmaf(p4.z, v2.w, fmaf(p4.w, v3.w, o[r][3]))));
            }
        }
    }

    // Normalize and write y[t, h*64 + d]
#pragma unroll
    for (int r = 0; r < 4; r++) {
        const float inv = 1.0f / l[r];
        const int row = qb * 64 + (ty << 2) + r;
        float4 out;
        out.x = o[r][0] * inv;
        out.y = o[r][1] * inv;
        out.z = o[r][2] * inv;
        out.w = o[r][3] * inv;
        *reinterpret_cast<float4*>(
            y + (size_t)row * C_DIM + h * HDIM + (tx << 2)) = out;
    }
}

// ---------------------------------------------------------------------------
// Launch: QKV GEMM -> causal attention -> output projection GEMM
// Inputs: x, mask(unused — deterministic causal), W_qkv, b_qkv, W_proj, b_proj
// ---------------------------------------------------------------------------
extern "C" void kernel_launch(void* const* d_in, const int* in_sizes, int n_in,
                              void* d_out, int out_size)
{
    (void)in_sizes; (void)n_in; (void)out_size;
    const float* x      = (const float*)d_in[0];
    const float* W_qkv  = (const float*)d_in[2];
    const float* b_qkv  = (const float*)d_in[3];
    const float* W_proj = (const float*)d_in[4];
    const float* b_proj = (const float*)d_in[5];
    float* out = (float*)d_out;

    float* qkv = nullptr;
    float* y   = nullptr;
    cudaGetSymbolAddress((void**)&qkv, g_qkv);
    cudaGetSymbolAddress((void**)&y, g_y);

    // 1) qkv = x @ W_qkv + b_qkv   [4096, 2304]
    dim3 g1(3 * C_DIM / 128, T_SEQ / 128);
    sgemm_bias<<<g1, 256>>>(x, W_qkv, b_qkv, qkv, T_SEQ, 3 * C_DIM, C_DIM);

    // 2) y = causal_attention(qkv)   [4096, 768]
    dim3 g2(T_SEQ / 64, NHEAD);
    attn_kernel<<<g2, 256>>>(qkv, y);

    // 3) out = y @ W_proj + b_proj   [4096, 768]
    dim3 g3(C_DIM / 128, T_SEQ / 128);
    sgemm_bias<<<g3, 256>>>(y, W_proj, b_proj, out, T_SEQ, C_DIM, C_DIM);
}

// round 3
// speedup vs baseline: 1.1927x; 1.1927x over previous
#include <cuda_runtime.h>
#include <math.h>

// Problem constants
#define T_SEQ 4096
#define C_DIM 768
#define NHEAD 12
#define HDIM  64
#define QKV_LD (3 * C_DIM)

// Scratch (allocation-guard-safe device globals)
__device__ float g_qkv[(size_t)T_SEQ * 3 * C_DIM];  // [T, 3C]: Q|K|V concatenated
__device__ float g_y[(size_t)T_SEQ * C_DIM];        // attention output [T, C]

// ---------------------------------------------------------------------------
// Classic 128x128x8 fp32 GEMM with bias: C[M,N] = A[M,K] @ B[K,N] + bias[N]
// 256 threads, 8x8 register tile per thread. Requires M%128==0, N%128==0, K%8==0.
// ---------------------------------------------------------------------------
__global__ __launch_bounds__(256) void sgemm_bias(
    const float* __restrict__ A, const float* __restrict__ B,
    const float* __restrict__ bias, float* __restrict__ Cmat,
    int M, int N, int K)
{
    __shared__ float As[8][128];   // A transposed: As[k][m]
    __shared__ float Bs[8][128];   // Bs[k][n]

    const int tid = threadIdx.x;
    const int tx = tid & 15;       // N-direction (8 cols each)
    const int ty = tid >> 4;       // M-direction (8 rows each)
    const int bx = blockIdx.x;     // N tile
    const int by = blockIdx.y;     // M tile

    float acc[8][8];
#pragma unroll
    for (int i = 0; i < 8; i++)
#pragma unroll
        for (int j = 0; j < 8; j++) acc[i][j] = 0.0f;

    const int aRow = tid >> 1;          // 0..127
    const int aCol = (tid & 1) * 4;     // 0 or 4
    const int bRow = tid >> 5;          // 0..7
    const int bCol = (tid & 31) * 4;    // 0..124

    const float* Ag = A + (size_t)(by * 128) * K;
    const float* Bg = B + (size_t)(bx * 128);

    for (int k0 = 0; k0 < K; k0 += 8) {
        float4 a4 = *reinterpret_cast<const float4*>(Ag + (size_t)aRow * K + k0 + aCol);
        As[aCol + 0][aRow] = a4.x;
        As[aCol + 1][aRow] = a4.y;
        As[aCol + 2][aRow] = a4.z;
        As[aCol + 3][aRow] = a4.w;
        float4 b4 = *reinterpret_cast<const float4*>(Bg + (size_t)(k0 + bRow) * N + bCol);
        *reinterpret_cast<float4*>(&Bs[bRow][bCol]) = b4;
        __syncthreads();

#pragma unroll
        for (int kk = 0; kk < 8; kk++) {
            float ar[8], br[8];
            *reinterpret_cast<float4*>(&ar[0]) = *reinterpret_cast<float4*>(&As[kk][ty * 8]);
            *reinterpret_cast<float4*>(&ar[4]) = *reinterpret_cast<float4*>(&As[kk][ty * 8 + 4]);
            *reinterpret_cast<float4*>(&br[0]) = *reinterpret_cast<float4*>(&Bs[kk][tx * 8]);
            *reinterpret_cast<float4*>(&br[4]) = *reinterpret_cast<float4*>(&Bs[kk][tx * 8 + 4]);
#pragma unroll
            for (int i = 0; i < 8; i++)
#pragma unroll
                for (int j = 0; j < 8; j++)
                    acc[i][j] = fmaf(ar[i], br[j], acc[i][j]);
        }
        __syncthreads();
    }

#pragma unroll
    for (int i = 0; i < 8; i++) {
        const int row = by * 128 + ty * 8 + i;
#pragma unroll
        for (int j = 0; j < 8; j += 4) {
            const int col = bx * 128 + tx * 8 + j;
            float4 o;
            o.x = acc[i][j + 0] + bias[col + 0];
            o.y = acc[i][j + 1] + bias[col + 1];
            o.z = acc[i][j + 2] + bias[col + 2];
            o.w = acc[i][j + 3] + bias[col + 3];
            *reinterpret_cast<float4*>(Cmat + (size_t)row * N + col) = o;
        }
    }
}

// ---------------------------------------------------------------------------
// Flash-style causal attention v2: 128x128 S tile, 8x8 per-thread fragment.
// 256 threads: tx = tid&15 (key/dim direction), ty = tid>>4 (query direction).
// Per-thread: rows q = ty + 16*r (r=0..7); S cols k = 64*g + tx*4 + c;
// O dims d = tx*4 + c (c=0..3).
// SMEM (dynamic, 164KB): Qs[128][68] natural (padded), Ks[128][64] with
// XOR-swizzled d-chunks (conflict-free row gather), Vs[128][64] natural,
// Ps[128][132] (padded P buffer).
// ---------------------------------------------------------------------------
#define QS_LD 68
#define P_LD  132
#define ATTN_SMEM_BYTES ((128 * QS_LD + 128 * 64 + 128 * 64 + 128 * P_LD) * 4)

__global__ __launch_bounds__(256, 1) void attn_kernel(
    const float* __restrict__ qkv, float* __restrict__ y)
{
    extern __shared__ float sm[];
    float* Qs = sm;                    // [128][QS_LD]
    float* Ks = Qs + 128 * QS_LD;      // [128][64], chunk-swizzled
    float* Vs = Ks + 128 * 64;         // [128][64]
    float* Ps = Vs + 128 * 64;         // [128][P_LD]

    const int qb  = 31 - (int)blockIdx.x;   // longest CTAs first
    const int h   = blockIdx.y;
    const int tid = threadIdx.x;
    const int tx  = tid & 15;
    const int ty  = tid >> 4;

    const float* Qg = qkv + h * HDIM;
    const float* Kg = qkv + C_DIM + h * HDIM;
    const float* Vg = qkv + 2 * C_DIM + h * HDIM;

    // Load Q block (natural layout, pre-scaled by 1/sqrt(D))
    for (int i = tid; i < 128 * 16; i += 256) {
        const int row = i >> 4;
        const int c4  = (i & 15) << 2;
        float4 q4 = *reinterpret_cast<const float4*>(
            Qg + (size_t)(qb * 128 + row) * QKV_LD + c4);
        float4 t;
        t.x = q4.x * 0.125f; t.y = q4.y * 0.125f;
        t.z = q4.z * 0.125f; t.w = q4.w * 0.125f;
        *reinterpret_cast<float4*>(Qs + row * QS_LD + c4) = t;
    }

    float o[8][4];
    float m[8], l[8];
#pragma unroll
    for (int r = 0; r < 8; r++) {
        m[r] = -INFINITY; l[r] = 0.0f;
#pragma unroll
        for (int c = 0; c < 4; c++) o[r][c] = 0.0f;
    }

    for (int kb = 0; kb <= qb; kb++) {
        __syncthreads();  // Q ready / previous iteration done with Ks,Vs,Ps
        // Load K (chunk-swizzled) and V (natural)
        for (int i = tid; i < 128 * 16; i += 256) {
            const int row = i >> 4;
            const int cd  = i & 15;
            float4 k4 = *reinterpret_cast<const float4*>(
                Kg + (size_t)(kb * 128 + row) * QKV_LD + (cd << 2));
            *reinterpret_cast<float4*>(
                Ks + (row << 6) + ((cd ^ ((row >> 2) & 15)) << 2)) = k4;
            float4 v4 = *reinterpret_cast<const float4*>(
                Vg + (size_t)(kb * 128 + row) * QKV_LD + (cd << 2));
            *reinterpret_cast<float4*>(Vs + (row << 6) + (cd << 2)) = v4;
        }
        __syncthreads();

        // ---- S = (Q*scale) @ K^T : dot products over d, 8x8 per thread ----
        float s[8][8];
#pragma unroll
        for (int r = 0; r < 8; r++)
#pragma unroll
            for (int c = 0; c < 8; c++) s[r][c] = 0.0f;

#pragma unroll 2
        for (int cd = 0; cd < 16; cd++) {
            float4 q[8];
#pragma unroll
            for (int r = 0; r < 8; r++)
                q[r] = *reinterpret_cast<float4*>(
                    Qs + (ty + (r << 4)) * QS_LD + (cd << 2));
            const int kchunk = (cd ^ tx) << 2;  // swizzled physical d-chunk
#pragma unroll
            for (int g = 0; g < 2; g++) {
#pragma unroll
                for (int c = 0; c < 4; c++) {
                    const int k = (g << 6) + (tx << 2) + c;
                    const float4 kv = *reinterpret_cast<float4*>(
                        Ks + (k << 6) + kchunk);
#pragma unroll
                    for (int r = 0; r < 8; r++) {
                        float acc = s[r][(g << 2) + c];
                        acc = fmaf(q[r].x, kv.x, acc);
                        acc = fmaf(q[r].y, kv.y, acc);
                        acc = fmaf(q[r].z, kv.z, acc);
                        acc = fmaf(q[r].w, kv.w, acc);
                        s[r][(g << 2) + c] = acc;
                    }
                }
            }
        }

        // Causal mask on the diagonal block only
        if (kb == qb) {
#pragma unroll
            for (int r = 0; r < 8; r++) {
                const int row = ty + (r << 4);
#pragma unroll
                for (int g = 0; g < 2; g++)
#pragma unroll
                    for (int c = 0; c < 4; c++)
                        if ((g << 6) + (tx << 2) + c > row)
                            s[r][(g << 2) + c] = -1e30f;
            }
        }

        // ---- Online softmax (row stats reduced over the 16 tx lanes) ----
        float corr[8];
#pragma unroll
        for (int r = 0; r < 8; r++) {
            float mx = s[r][0];
#pragma unroll
            for (int c = 1; c < 8; c++) mx = fmaxf(mx, s[r][c]);
#pragma unroll
            for (int off = 8; off >= 1; off >>= 1)
                mx = fmaxf(mx, __shfl_xor_sync(0xffffffffu, mx, off));
            const float mn = fmaxf(m[r], mx);
            corr[r] = __expf(m[r] - mn);
            float rs = 0.0f;
#pragma unroll
            for (int c = 0; c < 8; c++) {
                s[r][c] = __expf(s[r][c] - mn);
                rs += s[r][c];
            }
#pragma unroll
            for (int off = 8; off >= 1; off >>= 1)
                rs += __shfl_xor_sync(0xffffffffu, rs, off);
            l[r] = l[r] * corr[r] + rs;
            m[r] = mn;
#pragma unroll
            for (int c = 0; c < 4; c++) o[r][c] *= corr[r];
        }

        // ---- Store P (natural columns, padded stride) ----
#pragma unroll
        for (int r = 0; r < 8; r++) {
            float* prow = Ps + (ty + (r << 4)) * P_LD;
            float4 p0 = make_float4(s[r][0], s[r][1], s[r][2], s[r][3]);
            float4 p1 = make_float4(s[r][4], s[r][5], s[r][6], s[r][7]);
            *reinterpret_cast<float4*>(prow + (tx << 2)) = p0;
            *reinterpret_cast<float4*>(prow + 64 + (tx << 2)) = p1;
        }
        __syncthreads();

        // ---- O += P @ V ----
        for (int k0 = 0; k0 < 128; k0 += 4) {
            float4 v0 = *reinterpret_cast<float4*>(Vs + ((k0 + 0) << 6) + (tx << 2));
            float4 v1 = *reinterpret_cast<float4*>(Vs + ((k0 + 1) << 6) + (tx << 2));
            float4 v2 = *reinterpret_cast<float4*>(Vs + ((k0 + 2) << 6) + (tx << 2));
            float4 v3 = *reinterpret_cast<float4*>(Vs + ((k0 + 3) << 6) + (tx << 2));
#pragma unroll
            for (int r = 0; r < 8; r++) {
                const float4 p = *reinterpret_cast<float4*>(
                    Ps + (ty + (r << 4)) * P_LD + k0);
                o[r][0] = fmaf(p.x, v0.x, fmaf(p.y, v1.x, fmaf(p.z, v2.x, fmaf(p.w, v3.x, o[r][0]))));
                o[r][1] = fmaf(p.x, v0.y, fmaf(p.y, v1.y, fmaf(p.z, v2.y, fmaf(p.w, v3.y, o[r][1]))));
                o[r][2] = fmaf(p.x, v0.z, fmaf(p.y, v1.z, fmaf(p.z, v2.z, fmaf(p.w, v3.z, o[r][2]))));
                o[r][3] = fmaf(p.x, v0.w, fmaf(p.y, v1.w, fmaf(p.z, v2.w, fmaf(p.w, v3.w, o[r][3]))));
            }
        }
    }

    // Normalize and write y[t, h*64 + d]
#pragma unroll
    for (int r = 0; r < 8; r++) {
        const float inv = 1.0f / l[r];
        const int row = qb * 128 + ty + (r << 4);
        float4 out;
        out.x = o[r][0] * inv;
        out.y = o[r][1] * inv;
        out.z = o[r][2] * inv;
        out.w = o[r][3] * inv;
        *reinterpret_cast<float4*>(
            y + (size_t)row * C_DIM + h * HDIM + (tx << 2)) = out;
    }
}

// ---------------------------------------------------------------------------
// Launch: QKV GEMM -> causal attention -> output projection GEMM
// Inputs: x, mask(unused — deterministic causal), W_qkv, b_qkv, W_proj, b_proj
// ---------------------------------------------------------------------------
extern "C" void kernel_launch(void* const* d_in, const int* in_sizes, int n_in,
                              void* d_out, int out_size)
{
    (void)in_sizes; (void)n_in; (void)out_size;
    const float* x      = (const float*)d_in[0];
    const float* W_qkv  = (const float*)d_in[2];
    const float* b_qkv  = (const float*)d_in[3];
    const float* W_proj = (const float*)d_in[4];
    const float* b_proj = (const float*)d_in[5];
    float* out = (float*)d_out;

    float* qkv = nullptr;
    float* y   = nullptr;
    cudaGetSymbolAddress((void**)&qkv, g_qkv);
    cudaGetSymbolAddress((void**)&y, g_y);

    cudaFuncSetAttribute(attn_kernel,
                         cudaFuncAttributeMaxDynamicSharedMemorySize,
                         ATTN_SMEM_BYTES);

    // 1) qkv = x @ W_qkv + b_qkv   [4096, 2304]
    dim3 g1(3 * C_DIM / 128, T_SEQ / 128);
    sgemm_bias<<<g1, 256>>>(x, W_qkv, b_qkv, qkv, T_SEQ, 3 * C_DIM, C_DIM);

    // 2) y = causal_attention(qkv)   [4096, 768]
    dim3 g2(T_SEQ / 128, NHEAD);
    attn_kernel<<<g2, 256, ATTN_SMEM_BYTES>>>(qkv, y);

    // 3) out = y @ W_proj + b_proj   [4096, 768]
    dim3 g3(C_DIM / 128, T_SEQ / 128);
    sgemm_bias<<<g3, 256>>>(y, W_proj, b_proj, out, T_SEQ, C_DIM, C_DIM);
}

// round 6
// speedup vs baseline: 3.0111x; 2.5246x over previous
#include <cuda_runtime.h>
#include <cuda_bf16.h>
#include <math.h>
#include <stdint.h>

// Problem constants
#define T_SEQ 4096
#define C_DIM 768
#define NHEAD 12
#define HDIM  64
#define QKV3  (3 * C_DIM)

// ---------------------------------------------------------------------------
// Scratch (allocation-guard-safe device globals) — all bf16 hi/lo split pairs
// ---------------------------------------------------------------------------
__device__ __nv_bfloat16 g_xh[(size_t)T_SEQ * C_DIM];
__device__ __nv_bfloat16 g_xl[(size_t)T_SEQ * C_DIM];
__device__ __nv_bfloat16 g_qkvh[(size_t)T_SEQ * QKV3];
__device__ __nv_bfloat16 g_qkvl[(size_t)T_SEQ * QKV3];
__device__ __nv_bfloat16 g_yh[(size_t)T_SEQ * C_DIM];
__device__ __nv_bfloat16 g_yl[(size_t)T_SEQ * C_DIM];
__device__ __nv_bfloat16 g_wqh[(size_t)QKV3 * C_DIM];   // W_qkv^T [3C][C]
__device__ __nv_bfloat16 g_wql[(size_t)QKV3 * C_DIM];
__device__ __nv_bfloat16 g_wph[(size_t)C_DIM * C_DIM];  // W_proj^T [C][C]
__device__ __nv_bfloat16 g_wpl[(size_t)C_DIM * C_DIM];

// ---------------------------------------------------------------------------
// MMA / ldmatrix helpers (sm_80+ PTX; assembles on plain sm_103)
// ---------------------------------------------------------------------------
__device__ __forceinline__ uint32_t smem_u32(const void* p) {
    uint32_t a;
    asm("{ .reg .u64 t; cvta.to.shared.u64 t, %1; cvt.u32.u64 %0, t; }"
        : "=r"(a) : "l"(p));
    return a;
}
__device__ __forceinline__ void mma_bf16(float* c, const uint32_t* a,
                                         const uint32_t* b) {
    asm volatile(
        "mma.sync.aligned.m16n8k16.row.col.f32.bf16.bf16.f32 "
        "{%0,%1,%2,%3}, {%4,%5,%6,%7}, {%8,%9}, {%0,%1,%2,%3};"
        : "+f"(c[0]), "+f"(c[1]), "+f"(c[2]), "+f"(c[3])
        : "r"(a[0]), "r"(a[1]), "r"(a[2]), "r"(a[3]), "r"(b[0]), "r"(b[1]));
}
__device__ __forceinline__ void ldsm_x4(uint32_t* r, uint32_t a) {
    asm volatile("ldmatrix.sync.aligned.m8n8.x4.shared.b16 {%0,%1,%2,%3}, [%4];"
                 : "=r"(r[0]), "=r"(r[1]), "=r"(r[2]), "=r"(r[3]) : "r"(a));
}
__device__ __forceinline__ void ldsm_x4_t(uint32_t* r, uint32_t a) {
    asm volatile("ldmatrix.sync.aligned.m8n8.x4.trans.shared.b16 {%0,%1,%2,%3}, [%4];"
                 : "=r"(r[0]), "=r"(r[1]), "=r"(r[2]), "=r"(r[3]) : "r"(a));
}
// pack two f32 -> bf16x2 (lo -> low half, hi -> high half)
__device__ __forceinline__ uint32_t packbf(float lo, float hi) {
    uint32_t d;
    asm("cvt.rn.bf16x2.f32 %0, %1, %2;" : "=r"(d) : "f"(hi), "f"(lo));
    return d;
}
__device__ __forceinline__ float lo_f(uint32_t u) { return __uint_as_float(u << 16); }
__device__ __forceinline__ float hi_f(uint32_t u) { return __uint_as_float(u & 0xffff0000u); }

// byte offset into a [128][64]-bf16 tile with chunk-XOR swizzle (16B chunks)
__device__ __forceinline__ uint32_t sw_off(int row, int chunk) {
    return (uint32_t)((row << 7) + (((chunk ^ row) & 7) << 4) + ((chunk & ~7) << 4));
}

// ---------------------------------------------------------------------------
// Prep: fp32 -> bf16 hi/lo split (float4 granularity)
// ---------------------------------------------------------------------------
__global__ __launch_bounds__(256) void split_f32(
    const float* __restrict__ X, __nv_bfloat16* __restrict__ Xh,
    __nv_bfloat16* __restrict__ Xl, int n4)
{
    int i = blockIdx.x * 256 + threadIdx.x;
    if (i >= n4) return;
    float4 x = reinterpret_cast<const float4*>(X)[i];
    uint32_t h0 = packbf(x.x, x.y);
    uint32_t h1 = packbf(x.z, x.w);
    uint32_t l0 = packbf(x.x - lo_f(h0), x.y - hi_f(h0));
    uint32_t l1 = packbf(x.z - lo_f(h1), x.w - hi_f(h1));
    reinterpret_cast<uint2*>(Xh)[i] = make_uint2(h0, h1);
    reinterpret_cast<uint2*>(Xl)[i] = make_uint2(l0, l1);
}

// ---------------------------------------------------------------------------
// Prep: W[K][N] -> Wt hi/lo [N][K]
// ---------------------------------------------------------------------------
__global__ __launch_bounds__(256) void transpose_split(
    const float* __restrict__ W, __nv_bfloat16* __restrict__ Th,
    __nv_bfloat16* __restrict__ Tl, int K, int N)
{
    __shared__ float tile[32][33];
    const int tx = threadIdx.x & 31;
    const int ty = threadIdx.x >> 5;
    const int n0 = blockIdx.x * 32;
    const int k0 = blockIdx.y * 32;
#pragma unroll
    for (int i = 0; i < 4; i++)
        tile[ty + 8 * i][tx] = W[(size_t)(k0 + ty + 8 * i) * N + n0 + tx];
    __syncthreads();
#pragma unroll
    for (int i = 0; i < 4; i++) {
        const float v = tile[tx][ty + 8 * i];
        const float h = __bfloat162float(__float2bfloat16_rn(v));
        const size_t o = (size_t)(n0 + ty + 8 * i) * K + k0 + tx;
        Th[o] = __float2bfloat16_rn(h);
        Tl[o] = __float2bfloat16_rn(v - h);
    }
}

// ---------------------------------------------------------------------------
// Split-bf16 HMMA GEMM: C[M,N] = (Ah+Al)[M,K] @ ((Bh+Bl)[N,K])^T + bias
// CTA 128x128, k-chunk 64, 8 warps (4 m-strips x 2 n-strips), warp tile 32x64.
// mode=1: write bf16 hi/lo to Ch/Cl, scaling cols<C_DIM by 0.125 (QKV path).
// mode=0: write fp32 to Cf.
// ---------------------------------------------------------------------------
#define GEMM_SMEM (4 * 16384)

__global__ __launch_bounds__(256) void gemm_mma(
    const __nv_bfloat16* __restrict__ Ah, const __nv_bfloat16* __restrict__ Al,
    const __nv_bfloat16* __restrict__ Bh, const __nv_bfloat16* __restrict__ Bl,
    const float* __restrict__ bias, float* __restrict__ Cf,
    __nv_bfloat16* __restrict__ Ch, __nv_bfloat16* __restrict__ Cl,
    int M, int N, int K, int mode)
{
    extern __shared__ char smb[];
    char* sAh = smb;
    char* sAl = smb + 16384;
    char* sBh = smb + 32768;
    char* sBl = smb + 49152;
    const uint32_t uAh = smem_u32(sAh), uAl = smem_u32(sAl);
    const uint32_t uBh = smem_u32(sBh), uBl = smem_u32(sBl);

    const int tid = threadIdx.x;
    const int w = tid >> 5, lane = tid & 31;
    const int g = lane >> 2, t = lane & 3;
    const int wm = w & 3, wn = w >> 2;
    const int by = blockIdx.y, bx = blockIdx.x;

    float acc[2][8][4];
#pragma unroll
    for (int mi = 0; mi < 2; mi++)
#pragma unroll
        for (int nb = 0; nb < 8; nb++)
#pragma unroll
            for (int c = 0; c < 4; c++) acc[mi][nb][c] = 0.0f;

    // ldmatrix lane address components
    const int a_row = (lane & 15);
    const int a_chs = (lane >> 4);
    const int b_row = (lane & 7) + ((lane >> 4) << 3);
    const int b_chs = (lane >> 3) & 1;

    for (int k0 = 0; k0 < K; k0 += 64) {
        __syncthreads();
#pragma unroll 4
        for (int i = tid; i < 1024; i += 256) {
            const int row = i >> 3, ch = i & 7;
            const size_t ga = (size_t)(by * 128 + row) * K + k0 + ch * 8;
            const size_t gb = (size_t)(bx * 128 + row) * K + k0 + ch * 8;
            const uint32_t so = sw_off(row, ch);
            *reinterpret_cast<uint4*>(sAh + so) = *reinterpret_cast<const uint4*>(Ah + ga);
            *reinterpret_cast<uint4*>(sAl + so) = *reinterpret_cast<const uint4*>(Al + ga);
            *reinterpret_cast<uint4*>(sBh + so) = *reinterpret_cast<const uint4*>(Bh + gb);
            *reinterpret_cast<uint4*>(sBl + so) = *reinterpret_cast<const uint4*>(Bl + gb);
        }
        __syncthreads();

#pragma unroll
        for (int ks = 0; ks < 4; ks++) {
            uint32_t ah[2][4], al[2][4];
#pragma unroll
            for (int mi = 0; mi < 2; mi++) {
                const uint32_t so = sw_off(wm * 32 + mi * 16 + a_row, 2 * ks + a_chs);
                ldsm_x4(ah[mi], uAh + so);
                ldsm_x4(al[mi], uAl + so);
            }
#pragma unroll
            for (int nb = 0; nb < 8; nb += 2) {
                uint32_t bh4[4], bl4[4];
                const uint32_t so = sw_off(wn * 64 + nb * 8 + b_row, 2 * ks + b_chs);
                ldsm_x4(bh4, uBh + so);
                ldsm_x4(bl4, uBl + so);
#pragma unroll
                for (int mi = 0; mi < 2; mi++) {
                    mma_bf16(acc[mi][nb], ah[mi], bh4);
                    mma_bf16(acc[mi][nb], al[mi], bh4);
                    mma_bf16(acc[mi][nb], ah[mi], bl4);
                    mma_bf16(acc[mi][nb + 1], ah[mi], bh4 + 2);
                    mma_bf16(acc[mi][nb + 1], al[mi], bh4 + 2);
                    mma_bf16(acc[mi][nb + 1], ah[mi], bl4 + 2);
                }
            }
        }
    }

    // Epilogue
#pragma unroll
    for (int mi = 0; mi < 2; mi++) {
#pragma unroll
        for (int nb = 0; nb < 8; nb++) {
            const int row = by * 128 + wm * 32 + mi * 16 + g;
            const int col = bx * 128 + wn * 64 + nb * 8 + t * 2;
            const float2 bb = *reinterpret_cast<const float2*>(bias + col);
            float v0 = acc[mi][nb][0] + bb.x;
            float v1 = acc[mi][nb][1] + bb.y;
            float v2 = acc[mi][nb][2] + bb.x;
            float v3 = acc[mi][nb][3] + bb.y;
            if (mode) {
                const float sc = (col < C_DIM) ? 0.125f : 1.0f;  // pre-scale Q
                v0 *= sc; v1 *= sc; v2 *= sc; v3 *= sc;
                uint32_t h0 = packbf(v0, v1);
                uint32_t l0 = packbf(v0 - lo_f(h0), v1 - hi_f(h0));
                uint32_t h1 = packbf(v2, v3);
                uint32_t l1 = packbf(v2 - lo_f(h1), v3 - hi_f(h1));
                *reinterpret_cast<uint32_t*>(Ch + (size_t)row * N + col) = h0;
                *reinterpret_cast<uint32_t*>(Cl + (size_t)row * N + col) = l0;
                *reinterpret_cast<uint32_t*>(Ch + (size_t)(row + 8) * N + col) = h1;
                *reinterpret_cast<uint32_t*>(Cl + (size_t)(row + 8) * N + col) = l1;
            } else {
                *reinterpret_cast<float2*>(Cf + (size_t)row * N + col) =
                    make_float2(v0, v1);
                *reinterpret_cast<float2*>(Cf + (size_t)(row + 8) * N + col) =
                    make_float2(v2, v3);
            }
        }
    }
}

// ---------------------------------------------------------------------------
// Flash attention, split-bf16 HMMA. CTA = 128 q-rows x 1 head; 8 warps, each
// owns 16 q-rows. K/V blocks of 128 keys. P stays in registers (C->A refrag).
// ---------------------------------------------------------------------------
#define ATT_SMEM (6 * 16384)

__global__ __launch_bounds__(256, 1) void attn_mma(
    const __nv_bfloat16* __restrict__ qkvh, const __nv_bfloat16* __restrict__ qkvl,
    __nv_bfloat16* __restrict__ yh, __nv_bfloat16* __restrict__ yl)
{
    extern __shared__ char smb[];
    char* Qh = smb;
    char* Ql = smb + 16384;
    char* Kh = smb + 32768;
    char* Kl = smb + 49152;
    char* Vh = smb + 65536;
    char* Vl = smb + 81920;
    const uint32_t uQh = smem_u32(Qh), uQl = smem_u32(Ql);
    const uint32_t uKh = smem_u32(Kh), uKl = smem_u32(Kl);
    const uint32_t uVh = smem_u32(Vh), uVl = smem_u32(Vl);

    const int qb = 31 - (int)blockIdx.x;   // long CTAs first
    const int h = blockIdx.y;
    const int tid = threadIdx.x;
    const int w = tid >> 5, lane = tid & 31;
    const int g = lane >> 2, t = lane & 3;
    const int r0 = w * 16;

    const size_t qoff = (size_t)h * HDIM;
    const size_t koff = C_DIM + (size_t)h * HDIM;
    const size_t voff = 2 * C_DIM + (size_t)h * HDIM;

    // Load Q tile (Q already pre-scaled by 1/sqrt(D) in GEMM1 epilogue)
#pragma unroll 4
    for (int i = tid; i < 1024; i += 256) {
        const int row = i >> 3, ch = i & 7;
        const size_t gq = (size_t)(qb * 128 + row) * QKV3 + qoff + ch * 8;
        const uint32_t so = sw_off(row, ch);
        *reinterpret_cast<uint4*>(Qh + so) = *reinterpret_cast<const uint4*>(qkvh + gq);
        *reinterpret_cast<uint4*>(Ql + so) = *reinterpret_cast<const uint4*>(qkvl + gq);
    }
    __syncthreads();

    // Q fragments (held in registers for the whole kernel)
    uint32_t qfh[4][4], qfl[4][4];
    {
        const int arow = r0 + (lane & 15);
        const int achs = (lane >> 4);
#pragma unroll
        for (int ks = 0; ks < 4; ks++) {
            ldsm_x4(qfh[ks], uQh + sw_off(arow, 2 * ks + achs));
            ldsm_x4(qfl[ks], uQl + sw_off(arow, 2 * ks + achs));
        }
    }

    float o[8][4];
#pragma unroll
    for (int nb = 0; nb < 8; nb++)
#pragma unroll
        for (int c = 0; c < 4; c++) o[nb][c] = 0.0f;
    float m0r = -INFINITY, m1r = -INFINITY, l0r = 0.0f, l1r = 0.0f;

    const int b_row = (lane & 7) + ((lane >> 4) << 3);
    const int b_chs = (lane >> 3) & 1;
    const int v_row = (lane & 7) + (((lane >> 3) & 1) << 3);
    const int v_chs = (lane >> 4);

    for (int kb = 0; kb <= qb; kb++) {
        __syncthreads();
#pragma unroll 4
        for (int i = tid; i < 1024; i += 256) {
            const int row = i >> 3, ch = i & 7;
            const size_t gk = (size_t)(kb * 128 + row) * QKV3 + koff + ch * 8;
            const size_t gv = (size_t)(kb * 128 + row) * QKV3 + voff + ch * 8;
            const uint32_t so = sw_off(row, ch);
            *reinterpret_cast<uint4*>(Kh + so) = *reinterpret_cast<const uint4*>(qkvh + gk);
            *reinterpret_cast<uint4*>(Kl + so) = *reinterpret_cast<const uint4*>(qkvl + gk);
            *reinterpret_cast<uint4*>(Vh + so) = *reinterpret_cast<const uint4*>(qkvh + gv);
            *reinterpret_cast<uint4*>(Vl + so) = *reinterpret_cast<const uint4*>(qkvl + gv);
        }
        __syncthreads();

        // ---- S = Q @ K^T (16 n-blocks of 8 keys) ----
        float s[16][4];
#pragma unroll
        for (int nb = 0; nb < 16; nb++)
#pragma unroll
            for (int c = 0; c < 4; c++) s[nb][c] = 0.0f;

#pragma unroll
        for (int nb = 0; nb < 16; nb += 2) {
#pragma unroll
            for (int ks = 0; ks < 4; ks++) {
                uint32_t kh4[4], kl4[4];
                const uint32_t so = sw_off(nb * 8 + b_row, 2 * ks + b_chs);
                ldsm_x4(kh4, uKh + so);
                ldsm_x4(kl4, uKl + so);
                mma_bf16(s[nb], qfh[ks], kh4);
                mma_bf16(s[nb], qfl[ks], kh4);
                mma_bf16(s[nb], qfh[ks], kl4);
                mma_bf16(s[nb + 1], qfh[ks], kh4 + 2);
                mma_bf16(s[nb + 1], qfl[ks], kh4 + 2);
                mma_bf16(s[nb + 1], qfh[ks], kl4 + 2);
            }
        }

        // ---- causal mask on the diagonal block ----
        if (kb == qb) {
            const int ra = r0 + g, rb = r0 + g + 8;
#pragma unroll
            for (int nb = 0; nb < 16; nb++) {
                const int cb = nb * 8 + t * 2;
                if (cb > ra)     s[nb][0] = -1e30f;
                if (cb + 1 > ra) s[nb][1] = -1e30f;
                if (cb > rb)     s[nb][2] = -1e30f;
                if (cb + 1 > rb) s[nb][3] = -1e30f;
            }
        }

        // ---- online softmax (rows g / g+8; reduce across the 4-lane quad) ----
        float mx0 = -INFINITY, mx1 = -INFINITY;
#pragma unroll
        for (int nb = 0; nb < 16; nb++) {
            mx0 = fmaxf(mx0, fmaxf(s[nb][0], s[nb][1]));
            mx1 = fmaxf(mx1, fmaxf(s[nb][2], s[nb][3]));
        }
        mx0 = fmaxf(mx0, __shfl_xor_sync(0xffffffffu, mx0, 1));
        mx0 = fmaxf(mx0, __shfl_xor_sync(0xffffffffu, mx0, 2));
        mx1 = fmaxf(mx1, __shfl_xor_sync(0xffffffffu, mx1, 1));
        mx1 = fmaxf(mx1, __shfl_xor_sync(0xffffffffu, mx1, 2));
        const float mn0 = fmaxf(m0r, mx0);
        const float mn1 = fmaxf(m1r, mx1);
        const float c0 = __expf(m0r - mn0);
        const float c1 = __expf(m1r - mn1);
        float sum0 = 0.0f, sum1 = 0.0f;
#pragma unroll
        for (int nb = 0; nb < 16; nb++) {
            s[nb][0] = __expf(s[nb][0] - mn0);
            s[nb][1] = __expf(s[nb][1] - mn0);
            s[nb][2] = __expf(s[nb][2] - mn1);
            s[nb][3] = __expf(s[nb][3] - mn1);
            sum0 += s[nb][0] + s[nb][1];
            sum1 += s[nb][2] + s[nb][3];
        }
        sum0 += __shfl_xor_sync(0xffffffffu, sum0, 1);
        sum0 += __shfl_xor_sync(0xffffffffu, sum0, 2);
        sum1 += __shfl_xor_sync(0xffffffffu, sum1, 1);
        sum1 += __shfl_xor_sync(0xffffffffu, sum1, 2);
        l0r = l0r * c0 + sum0;
        l1r = l1r * c1 + sum1;
        m0r = mn0; m1r = mn1;
#pragma unroll
        for (int nb = 0; nb < 8; nb++) {
            o[nb][0] *= c0; o[nb][1] *= c0;
            o[nb][2] *= c1; o[nb][3] *= c1;
        }

        // ---- O += P @ V (P refragmented from S C-frags, split hi/lo) ----
#pragma unroll
        for (int kk = 0; kk < 8; kk++) {
            uint32_t ph[4], pl[4];
            ph[0] = packbf(s[2 * kk][0], s[2 * kk][1]);
            pl[0] = packbf(s[2 * kk][0] - lo_f(ph[0]), s[2 * kk][1] - hi_f(ph[0]));
            ph[1] = packbf(s[2 * kk][2], s[2 * kk][3]);
            pl[1] = packbf(s[2 * kk][2] - lo_f(ph[1]), s[2 * kk][3] - hi_f(ph[1]));
            ph[2] = packbf(s[2 * kk + 1][0], s[2 * kk + 1][1]);
            pl[2] = packbf(s[2 * kk + 1][0] - lo_f(ph[2]), s[2 * kk + 1][1] - hi_f(ph[2]));
            ph[3] = packbf(s[2 * kk + 1][2], s[2 * kk + 1][3]);
            pl[3] = packbf(s[2 * kk + 1][2] - lo_f(ph[3]), s[2 * kk + 1][3] - hi_f(ph[3]));
#pragma unroll
            for (int nb = 0; nb < 8; nb += 2) {
                uint32_t vh4[4], vl4[4];
                const uint32_t so = sw_off(kk * 16 + v_row, nb + v_chs);
                ldsm_x4_t(vh4, uVh + so);
                ldsm_x4_t(vl4, uVl + so);
                mma_bf16(o[nb], ph, vh4);
                mma_bf16(o[nb], pl, vh4);
                mma_bf16(o[nb], ph, vl4);
                mma_bf16(o[nb + 1], ph, vh4 + 2);
                mma_bf16(o[nb + 1], pl, vh4 + 2);
                mma_bf16(o[nb + 1], ph, vl4 + 2);
            }
        }
    }

    // ---- normalize and write y (bf16 hi/lo split) ----
    const float inv0 = 1.0f / l0r;
    const float inv1 = 1.0f / l1r;
    const int row0 = qb * 128 + r0 + g;
    const int row1 = row0 + 8;
#pragma unroll
    for (int nb = 0; nb < 8; nb++) {
        const int col = h * HDIM + nb * 8 + t * 2;
        float a0 = o[nb][0] * inv0, a1 = o[nb][1] * inv0;
        float b0 = o[nb][2] * inv1, b1 = o[nb][3] * inv1;
        uint32_t h0 = packbf(a0, a1);
        uint32_t l0 = packbf(a0 - lo_f(h0), a1 - hi_f(h0));
        uint32_t h1 = packbf(b0, b1);
        uint32_t l1 = packbf(b0 - lo_f(h1), b1 - hi_f(h1));
        *reinterpret_cast<uint32_t*>(yh + (size_t)row0 * C_DIM + col) = h0;
        *reinterpret_cast<uint32_t*>(yl + (size_t)row0 * C_DIM + col) = l0;
        *reinterpret_cast<uint32_t*>(yh + (size_t)row1 * C_DIM + col) = h1;
        *reinterpret_cast<uint32_t*>(yl + (size_t)row1 * C_DIM + col) = l1;
    }
}

// ---------------------------------------------------------------------------
// Launch
// ---------------------------------------------------------------------------
extern "C" void kernel_launch(void* const* d_in, const int* in_sizes, int n_in,
                              void* d_out, int out_size)
{
    (void)in_sizes; (void)n_in; (void)out_size;
    const float* x      = (const float*)d_in[0];
    const float* W_qkv  = (const float*)d_in[2];
    const float* b_qkv  = (const float*)d_in[3];
    const float* W_proj = (const float*)d_in[4];
    const float* b_proj = (const float*)d_in[5];
    float* out = (float*)d_out;

    __nv_bfloat16 *xh, *xl, *qkvh, *qkvl, *yh, *yl, *wqh, *wql, *wph, *wpl;
    cudaGetSymbolAddress((void**)&xh, g_xh);
    cudaGetSymbolAddress((void**)&xl, g_xl);
    cudaGetSymbolAddress((void**)&qkvh, g_qkvh);
    cudaGetSymbolAddress((void**)&qkvl, g_qkvl);
    cudaGetSymbolAddress((void**)&yh, g_yh);
    cudaGetSymbolAddress((void**)&yl, g_yl);
    cudaGetSymbolAddress((void**)&wqh, g_wqh);
    cudaGetSymbolAddress((void**)&wql, g_wql);
    cudaGetSymbolAddress((void**)&wph, g_wph);
    cudaGetSymbolAddress((void**)&wpl, g_wpl);

    cudaFuncSetAttribute(gemm_mma,
                         cudaFuncAttributeMaxDynamicSharedMemorySize, GEMM_SMEM);
    cudaFuncSetAttribute(attn_mma,
                         cudaFuncAttributeMaxDynamicSharedMemorySize, ATT_SMEM);

    // 0) prep: weight transpose+split, input split
    transpose_split<<<dim3(QKV3 / 32, C_DIM / 32), 256>>>(
        W_qkv, wqh, wql, C_DIM, QKV3);
    transpose_split<<<dim3(C_DIM / 32, C_DIM / 32), 256>>>(
        W_proj, wph, wpl, C_DIM, C_DIM);
    split_f32<<<(T_SEQ * C_DIM / 4 + 255) / 256, 256>>>(
        x, xh, xl, T_SEQ * C_DIM / 4);

    // 1) qkv = x @ W_qkv + b_qkv -> bf16 hi/lo, Q cols pre-scaled by 0.125
    gemm_mma<<<dim3(QKV3 / 128, T_SEQ / 128), 256, GEMM_SMEM>>>(
        xh, xl, wqh, wql, b_qkv, nullptr, qkvh, qkvl, T_SEQ, QKV3, C_DIM, 1);

    // 2) y = causal_attention(qkv) -> bf16 hi/lo
    attn_mma<<<dim3(T_SEQ / 128, NHEAD), 256, ATT_SMEM>>>(qkvh, qkvl, yh, yl);

    // 3) out = y @ W_proj + b_proj (fp32)
    gemm_mma<<<dim3(C_DIM / 128, T_SEQ / 128), 256, GEMM_SMEM>>>(
        yh, yl, wph, wpl, b_proj, out, nullptr, nullptr, T_SEQ, C_DIM, C_DIM, 0);
}

// round 8
// speedup vs baseline: 3.5975x; 1.1948x over previous
#include <cuda_runtime.h>
#include <cuda_bf16.h>
#include <math.h>
#include <stdint.h>

// Problem constants
#define T_SEQ 4096
#define C_DIM 768
#define NHEAD 12
#define HDIM  64
#define QKV3  (3 * C_DIM)

// ---------------------------------------------------------------------------
// Scratch (allocation-guard-safe device globals) — all bf16 hi/lo split pairs
// ---------------------------------------------------------------------------
__device__ __nv_bfloat16 g_xh[(size_t)T_SEQ * C_DIM];
__device__ __nv_bfloat16 g_xl[(size_t)T_SEQ * C_DIM];
__device__ __nv_bfloat16 g_qkvh[(size_t)T_SEQ * QKV3];
__device__ __nv_bfloat16 g_qkvl[(size_t)T_SEQ * QKV3];
__device__ __nv_bfloat16 g_yh[(size_t)T_SEQ * C_DIM];
__device__ __nv_bfloat16 g_yl[(size_t)T_SEQ * C_DIM];
__device__ __nv_bfloat16 g_wqh[(size_t)QKV3 * C_DIM];   // W_qkv^T [3C][C]
__device__ __nv_bfloat16 g_wql[(size_t)QKV3 * C_DIM];
__device__ __nv_bfloat16 g_wph[(size_t)C_DIM * C_DIM];  // W_proj^T [C][C]
__device__ __nv_bfloat16 g_wpl[(size_t)C_DIM * C_DIM];

// ---------------------------------------------------------------------------
// MMA / ldmatrix / cp.async helpers (sm_80+ PTX; assembles on plain sm_103)
// ---------------------------------------------------------------------------
__device__ __forceinline__ uint32_t smem_u32(const void* p) {
    uint32_t a;
    asm("{ .reg .u64 t; cvta.to.shared.u64 t, %1; cvt.u32.u64 %0, t; }"
        : "=r"(a) : "l"(p));
    return a;
}
__device__ __forceinline__ void mma_bf16(float* c, const uint32_t* a,
                                         const uint32_t* b) {
    asm volatile(
        "mma.sync.aligned.m16n8k16.row.col.f32.bf16.bf16.f32 "
        "{%0,%1,%2,%3}, {%4,%5,%6,%7}, {%8,%9}, {%0,%1,%2,%3};"
        : "+f"(c[0]), "+f"(c[1]), "+f"(c[2]), "+f"(c[3])
        : "r"(a[0]), "r"(a[1]), "r"(a[2]), "r"(a[3]), "r"(b[0]), "r"(b[1]));
}
__device__ __forceinline__ void ldsm_x4(uint32_t* r, uint32_t a) {
    asm volatile("ldmatrix.sync.aligned.m8n8.x4.shared.b16 {%0,%1,%2,%3}, [%4];"
                 : "=r"(r[0]), "=r"(r[1]), "=r"(r[2]), "=r"(r[3]) : "r"(a));
}
__device__ __forceinline__ void ldsm_x4_t(uint32_t* r, uint32_t a) {
    asm volatile("ldmatrix.sync.aligned.m8n8.x4.trans.shared.b16 {%0,%1,%2,%3}, [%4];"
                 : "=r"(r[0]), "=r"(r[1]), "=r"(r[2]), "=r"(r[3]) : "r"(a));
}
__device__ __forceinline__ void cp16(uint32_t dst, const void* src) {
    asm volatile("cp.async.cg.shared.global [%0], [%1], 16;"
                 :: "r"(dst), "l"(src));
}
#define CP_COMMIT() asm volatile("cp.async.commit_group;" ::: "memory")
#define CP_WAIT1()  asm volatile("cp.async.wait_group 1;" ::: "memory")
#define CP_WAIT0()  asm volatile("cp.async.wait_group 0;" ::: "memory")

// pack two f32 -> bf16x2 (lo -> low half, hi -> high half)
__device__ __forceinline__ uint32_t packbf(float lo, float hi) {
    uint32_t d;
    asm("cvt.rn.bf16x2.f32 %0, %1, %2;" : "=r"(d) : "f"(hi), "f"(lo));
    return d;
}
__device__ __forceinline__ float lo_f(uint32_t u) { return __uint_as_float(u << 16); }
__device__ __forceinline__ float hi_f(uint32_t u) { return __uint_as_float(u & 0xffff0000u); }

// byte offset into a [128][64]-bf16 tile with chunk-XOR swizzle (16B chunks)
__device__ __forceinline__ uint32_t sw_off(int row, int chunk) {
    return (uint32_t)((row << 7) + (((chunk ^ row) & 7) << 4) + ((chunk & ~7) << 4));
}

// ---------------------------------------------------------------------------
// Prep: fp32 -> bf16 hi/lo split (float4 granularity)
// ---------------------------------------------------------------------------
__global__ __launch_bounds__(256) void split_f32(
    const float* __restrict__ X, __nv_bfloat16* __restrict__ Xh,
    __nv_bfloat16* __restrict__ Xl, int n4)
{
    int i = blockIdx.x * 256 + threadIdx.x;
    if (i >= n4) return;
    float4 x = reinterpret_cast<const float4*>(X)[i];
    uint32_t h0 = packbf(x.x, x.y);
    uint32_t h1 = packbf(x.z, x.w);
    uint32_t l0 = packbf(x.x - lo_f(h0), x.y - hi_f(h0));
    uint32_t l1 = packbf(x.z - lo_f(h1), x.w - hi_f(h1));
    reinterpret_cast<uint2*>(Xh)[i] = make_uint2(h0, h1);
    reinterpret_cast<uint2*>(Xl)[i] = make_uint2(l0, l1);
}

// ---------------------------------------------------------------------------
// Prep: W[K][N] -> Wt hi/lo [N][K]
// ---------------------------------------------------------------------------
__global__ __launch_bounds__(256) void transpose_split(
    const float* __restrict__ W, __nv_bfloat16* __restrict__ Th,
    __nv_bfloat16* __restrict__ Tl, int K, int N)
{
    __shared__ float tile[32][33];
    const int tx = threadIdx.x & 31;
    const int ty = threadIdx.x >> 5;
    const int n0 = blockIdx.x * 32;
    const int k0 = blockIdx.y * 32;
#pragma unroll
    for (int i = 0; i < 4; i++)
        tile[ty + 8 * i][tx] = W[(size_t)(k0 + ty + 8 * i) * N + n0 + tx];
    __syncthreads();
#pragma unroll
    for (int i = 0; i < 4; i++) {
        const float v = tile[tx][ty + 8 * i];
        const float h = __bfloat162float(__float2bfloat16_rn(v));
        const size_t o = (size_t)(n0 + ty + 8 * i) * K + k0 + tx;
        Th[o] = __float2bfloat16_rn(h);
        Tl[o] = __float2bfloat16_rn(v - h);
    }
}

// ---------------------------------------------------------------------------
// Split-bf16 HMMA GEMM with cp.async 2-stage pipeline.
// C[M,N] = (Ah+Al)[M,K] @ ((Bh+Bl)[N,K])^T + bias
// CTA 128x128, k-chunk 64, 8 warps (4 m-strips x 2 n-strips), warp tile 32x64.
// mode=1: write bf16 hi/lo to Ch/Cl, scaling cols<C_DIM by 0.125 (QKV path).
// mode=0: write fp32 to Cf.
// ---------------------------------------------------------------------------
#define GEMM_SMEM (2 * 4 * 16384)

__global__ __launch_bounds__(256) void gemm_mma(
    const __nv_bfloat16* __restrict__ Ah, const __nv_bfloat16* __restrict__ Al,
    const __nv_bfloat16* __restrict__ Bh, const __nv_bfloat16* __restrict__ Bl,
    const float* __restrict__ bias, float* __restrict__ Cf,
    __nv_bfloat16* __restrict__ Ch, __nv_bfloat16* __restrict__ Cl,
    int M, int N, int K, int mode)
{
    extern __shared__ char smb[];
    const uint32_t ubase = smem_u32(smb);

    const int tid = threadIdx.x;
    const int w = tid >> 5, lane = tid & 31;
    const int g = lane >> 2, t = lane & 3;
    const int wm = w & 3, wn = w >> 2;
    const int by = blockIdx.y, bx = blockIdx.x;

    float acc[2][8][4];
#pragma unroll
    for (int mi = 0; mi < 2; mi++)
#pragma unroll
        for (int nb = 0; nb < 8; nb++)
#pragma unroll
            for (int c = 0; c < 4; c++) acc[mi][nb][c] = 0.0f;

    const int a_row = (lane & 15);
    const int a_chs = (lane >> 4);
    const int b_row = (lane & 7) + ((lane >> 4) << 3);
    const int b_chs = (lane >> 3) & 1;

    const int NI = K / 64;

    // async-load one 64KB stage (4 tiles)
    auto load_stage = [&](int st, int k0) {
        const uint32_t ub = ubase + st * 65536;
#pragma unroll
        for (int j = 0; j < 4; j++) {
            const int i = tid + 256 * j;
            const int row = i >> 3, ch = i & 7;
            const size_t ga = (size_t)(by * 128 + row) * K + k0 + ch * 8;
            const size_t gb = (size_t)(bx * 128 + row) * K + k0 + ch * 8;
            const uint32_t so = sw_off(row, ch);
            cp16(ub + so, Ah + ga);
            cp16(ub + 16384 + so, Al + ga);
            cp16(ub + 32768 + so, Bh + gb);
            cp16(ub + 49152 + so, Bl + gb);
        }
    };

    load_stage(0, 0);
    CP_COMMIT();

    for (int it = 0; it < NI; it++) {
        const int st = it & 1;
        if (it + 1 < NI) {
            load_stage(st ^ 1, (it + 1) * 64);
            CP_COMMIT();
            CP_WAIT1();
        } else {
            CP_WAIT0();
        }
        __syncthreads();

        const uint32_t uAh = ubase + st * 65536;
        const uint32_t uAl = uAh + 16384;
        const uint32_t uBh = uAh + 32768;
        const uint32_t uBl = uAh + 49152;

#pragma unroll
        for (int ks = 0; ks < 4; ks++) {
            uint32_t ah[2][4], al[2][4];
#pragma unroll
            for (int mi = 0; mi < 2; mi++) {
                const uint32_t so = sw_off(wm * 32 + mi * 16 + a_row, 2 * ks + a_chs);
                ldsm_x4(ah[mi], uAh + so);
                ldsm_x4(al[mi], uAl + so);
            }
#pragma unroll
            for (int nb = 0; nb < 8; nb += 2) {
                uint32_t bh4[4], bl4[4];
                const uint32_t so = sw_off(wn * 64 + nb * 8 + b_row, 2 * ks + b_chs);
                ldsm_x4(bh4, uBh + so);
                ldsm_x4(bl4, uBl + so);
#pragma unroll
                for (int mi = 0; mi < 2; mi++) {
                    mma_bf16(acc[mi][nb], ah[mi], bh4);
                    mma_bf16(acc[mi][nb], al[mi], bh4);
                    mma_bf16(acc[mi][nb], ah[mi], bl4);
                    mma_bf16(acc[mi][nb + 1], ah[mi], bh4 + 2);
                    mma_bf16(acc[mi][nb + 1], al[mi], bh4 + 2);
                    mma_bf16(acc[mi][nb + 1], ah[mi], bl4 + 2);
                }
            }
        }
        __syncthreads();
    }

    // Epilogue
#pragma unroll
    for (int mi = 0; mi < 2; mi++) {
#pragma unroll
        for (int nb = 0; nb < 8; nb++) {
            const int row = by * 128 + wm * 32 + mi * 16 + g;
            const int col = bx * 128 + wn * 64 + nb * 8 + t * 2;
            const float2 bb = *reinterpret_cast<const float2*>(bias + col);
            float v0 = acc[mi][nb][0] + bb.x;
            float v1 = acc[mi][nb][1] + bb.y;
            float v2 = acc[mi][nb][2] + bb.x;
            float v3 = acc[mi][nb][3] + bb.y;
            if (mode) {
                const float sc = (col < C_DIM) ? 0.125f : 1.0f;  // pre-scale Q
                v0 *= sc; v1 *= sc; v2 *= sc; v3 *= sc;
                uint32_t h0 = packbf(v0, v1);
                uint32_t l0 = packbf(v0 - lo_f(h0), v1 - hi_f(h0));
                uint32_t h1 = packbf(v2, v3);
                uint32_t l1 = packbf(v2 - lo_f(h1), v3 - hi_f(h1));
                *reinterpret_cast<uint32_t*>(Ch + (size_t)row * N + col) = h0;
                *reinterpret_cast<uint32_t*>(Cl + (size_t)row * N + col) = l0;
                *reinterpret_cast<uint32_t*>(Ch + (size_t)(row + 8) * N + col) = h1;
                *reinterpret_cast<uint32_t*>(Cl + (size_t)(row + 8) * N + col) = l1;
            } else {
                *reinterpret_cast<float2*>(Cf + (size_t)row * N + col) =
                    make_float2(v0, v1);
                *reinterpret_cast<float2*>(Cf + (size_t)(row + 8) * N + col) =
                    make_float2(v2, v3);
            }
        }
    }
}

// ---------------------------------------------------------------------------
// Flash attention, split-bf16 HMMA, cp.async 2-stage K/V pipeline.
// CTA = 128 q-rows x 1 head; 8 warps x 16 q-rows. P in registers.
// SMEM: Q (32KB) + 2 stages x (Kh,Kl,Vh,Vl) (64KB each) = 160KB.
// ---------------------------------------------------------------------------
#define ATT_SMEM (2 * 16384 + 2 * 4 * 16384)

__global__ __launch_bounds__(256, 1) void attn_mma(
    const __nv_bfloat16* __restrict__ qkvh, const __nv_bfloat16* __restrict__ qkvl,
    __nv_bfloat16* __restrict__ yh, __nv_bfloat16* __restrict__ yl)
{
    extern __shared__ char smb[];
    const uint32_t uQh = smem_u32(smb);
    const uint32_t uQl = uQh + 16384;
    const uint32_t uKV = uQh + 32768;   // stage s: +s*65536

    const int qb = 31 - (int)blockIdx.x;   // long CTAs first
    const int h = blockIdx.y;
    const int tid = threadIdx.x;
    const int w = tid >> 5, lane = tid & 31;
    const int g = lane >> 2, t = lane & 3;
    const int r0 = w * 16;

    const size_t qoff = (size_t)h * HDIM;
    const size_t koff = C_DIM + (size_t)h * HDIM;
    const size_t voff = 2 * C_DIM + (size_t)h * HDIM;

    auto load_kv = [&](int st, int kb) {
        const uint32_t ub = uKV + st * 65536;
#pragma unroll
        for (int j = 0; j < 4; j++) {
            const int i = tid + 256 * j;
            const int row = i >> 3, ch = i & 7;
            const size_t gk = (size_t)(kb * 128 + row) * QKV3 + koff + ch * 8;
            const size_t gv = (size_t)(kb * 128 + row) * QKV3 + voff + ch * 8;
            const uint32_t so = sw_off(row, ch);
            cp16(ub + so, qkvh + gk);
            cp16(ub + 16384 + so, qkvl + gk);
            cp16(ub + 32768 + so, qkvh + gv);
            cp16(ub + 49152 + so, qkvl + gv);
        }
    };

    // Prefetch K/V block 0, then load Q (regular STS) while DMA drains
    load_kv(0, 0);
    CP_COMMIT();
#pragma unroll 4
    for (int i = tid; i < 1024; i += 256) {
        const int row = i >> 3, ch = i & 7;
        const size_t gq = (size_t)(qb * 128 + row) * QKV3 + qoff + ch * 8;
        const uint32_t so = sw_off(row, ch);
        *reinterpret_cast<uint4*>(smb + so) =
            *reinterpret_cast<const uint4*>(qkvh + gq);
        *reinterpret_cast<uint4*>(smb + 16384 + so) =
            *reinterpret_cast<const uint4*>(qkvl + gq);
    }
    __syncthreads();

    // Q fragments (registers for the whole kernel)
    uint32_t qfh[4][4], qfl[4][4];
    {
        const int arow = r0 + (lane & 15);
        const int achs = (lane >> 4);
#pragma unroll
        for (int ks = 0; ks < 4; ks++) {
            ldsm_x4(qfh[ks], uQh + sw_off(arow, 2 * ks + achs));
            ldsm_x4(qfl[ks], uQl + sw_off(arow, 2 * ks + achs));
        }
    }

    float o[8][4];
#pragma unroll
    for (int nb = 0; nb < 8; nb++)
#pragma unroll
        for (int c = 0; c < 4; c++) o[nb][c] = 0.0f;
    float m0r = -INFINITY, m1r = -INFINITY, l0r = 0.0f, l1r = 0.0f;

    const int b_row = (lane & 7) + ((lane >> 4) << 3);
    const int b_chs = (lane >> 3) & 1;
    const int v_row = (lane & 7) + (((lane >> 3) & 1) << 3);
    const int v_chs = (lane >> 4);

    for (int kb = 0; kb <= qb; kb++) {
        const int st = kb & 1;
        if (kb + 1 <= qb) {
            load_kv(st ^ 1, kb + 1);
            CP_COMMIT();
            CP_WAIT1();
        } else {
            CP_WAIT0();
        }
        __syncthreads();

        const uint32_t uKh = uKV + st * 65536;
        const uint32_t uKl = uKh + 16384;
        const uint32_t uVh = uKh + 32768;
        const uint32_t uVl = uKh + 49152;

        // ---- S = Q @ K^T (16 n-blocks of 8 keys) ----
        float s[16][4];
#pragma unroll
        for (int nb = 0; nb < 16; nb++)
#pragma unroll
            for (int c = 0; c < 4; c++) s[nb][c] = 0.0f;

#pragma unroll
        for (int nb = 0; nb < 16; nb += 2) {
#pragma unroll
            for (int ks = 0; ks < 4; ks++) {
                uint32_t kh4[4], kl4[4];
                const uint32_t so = sw_off(nb * 8 + b_row, 2 * ks + b_chs);
                ldsm_x4(kh4, uKh + so);
                ldsm_x4(kl4, uKl + so);
                mma_bf16(s[nb], qfh[ks], kh4);
                mma_bf16(s[nb], qfl[ks], kh4);
                mma_bf16(s[nb], qfh[ks], kl4);
                mma_bf16(s[nb + 1], qfh[ks], kh4 + 2);
                mma_bf16(s[nb + 1], qfl[ks], kh4 + 2);
                mma_bf16(s[nb + 1], qfh[ks], kl4 + 2);
            }
        }

        // ---- causal mask on the diagonal block ----
        if (kb == qb) {
            const int ra = r0 + g, rb = r0 + g + 8;
#pragma unroll
            for (int nb = 0; nb < 16; nb++) {
                const int cb = nb * 8 + t * 2;
                if (cb > ra)     s[nb][0] = -1e30f;
                if (cb + 1 > ra) s[nb][1] = -1e30f;
                if (cb > rb)     s[nb][2] = -1e30f;
                if (cb + 1 > rb) s[nb][3] = -1e30f;
            }
        }

        // ---- online softmax (rows g / g+8; reduce across the 4-lane quad) ----
        float mx0 = -INFINITY, mx1 = -INFINITY;
#pragma unroll
        for (int nb = 0; nb < 16; nb++) {
            mx0 = fmaxf(mx0, fmaxf(s[nb][0], s[nb][1]));
            mx1 = fmaxf(mx1, fmaxf(s[nb][2], s[nb][3]));
        }
        mx0 = fmaxf(mx0, __shfl_xor_sync(0xffffffffu, mx0, 1));
        mx0 = fmaxf(mx0, __shfl_xor_sync(0xffffffffu, mx0, 2));
        mx1 = fmaxf(mx1, __shfl_xor_sync(0xffffffffu, mx1, 1));
        mx1 = fmaxf(mx1, __shfl_xor_sync(0xffffffffu, mx1, 2));
        const float mn0 = fmaxf(m0r, mx0);
        const float mn1 = fmaxf(m1r, mx1);
        const float c0 = __expf(m0r - mn0);
        const float c1 = __expf(m1r - mn1);
        float sum0 = 0.0f, sum1 = 0.0f;
#pragma unroll
        for (int nb = 0; nb < 16; nb++) {
            s[nb][0] = __expf(s[nb][0] - mn0);
            s[nb][1] = __expf(s[nb][1] - mn0);
            s[nb][2] = __expf(s[nb][2] - mn1);
            s[nb][3] = __expf(s[nb][3] - mn1);
            sum0 += s[nb][0] + s[nb][1];
            sum1 += s[nb][2] + s[nb][3];
        }
        sum0 += __shfl_xor_sync(0xffffffffu, sum0, 1);
        sum0 += __shfl_xor_sync(0xffffffffu, sum0, 2);
        sum1 += __shfl_xor_sync(0xffffffffu, sum1, 1);
        sum1 += __shfl_xor_sync(0xffffffffu, sum1, 2);
        l0r = l0r * c0 + sum0;
        l1r = l1r * c1 + sum1;
        m0r = mn0; m1r = mn1;
#pragma unroll
        for (int nb = 0; nb < 8; nb++) {
            o[nb][0] *= c0; o[nb][1] *= c0;
            o[nb][2] *= c1; o[nb][3] *= c1;
        }

        // ---- O += P @ V (P refragmented from S C-frags, split hi/lo) ----
#pragma unroll
        for (int kk = 0; kk < 8; kk++) {
            uint32_t ph[4], pl[4];
            ph[0] = packbf(s[2 * kk][0], s[2 * kk][1]);
            pl[0] = packbf(s[2 * kk][0] - lo_f(ph[0]), s[2 * kk][1] - hi_f(ph[0]));
            ph[1] = packbf(s[2 * kk][2], s[2 * kk][3]);
            pl[1] = packbf(s[2 * kk][2] - lo_f(ph[1]), s[2 * kk][3] - hi_f(ph[1]));
            ph[2] = packbf(s[2 * kk + 1][0], s[2 * kk + 1][1]);
            pl[2] = packbf(s[2 * kk + 1][0] - lo_f(ph[2]), s[2 * kk + 1][1] - hi_f(ph[2]));
            ph[3] = packbf(s[2 * kk + 1][2], s[2 * kk + 1][3]);
            pl[3] = packbf(s[2 * kk + 1][2] - lo_f(ph[3]), s[2 * kk + 1][3] - hi_f(ph[3]));
#pragma unroll
            for (int nb = 0; nb < 8; nb += 2) {
                uint32_t vh4[4], vl4[4];
                const uint32_t so = sw_off(kk * 16 + v_row, nb + v_chs);
                ldsm_x4_t(vh4, uVh + so);
                ldsm_x4_t(vl4, uVl + so);
                mma_bf16(o[nb], ph, vh4);
                mma_bf16(o[nb], pl, vh4);
                mma_bf16(o[nb], ph, vl4);
                mma_bf16(o[nb + 1], ph, vh4 + 2);
                mma_bf16(o[nb + 1], pl, vh4 + 2);
                mma_bf16(o[nb + 1], ph, vl4 + 2);
            }
        }
        __syncthreads();
    }

    // ---- normalize and write y (bf16 hi/lo split) ----
    const float inv0 = 1.0f / l0r;
    const float inv1 = 1.0f / l1r;
    const int row0 = qb * 128 + r0 + g;
    const int row1 = row0 + 8;
#pragma unroll
    for (int nb = 0; nb < 8; nb++) {
        const int col = h * HDIM + nb * 8 + t * 2;
        float a0 = o[nb][0] * inv0, a1 = o[nb][1] * inv0;
        float b0 = o[nb][2] * inv1, b1 = o[nb][3] * inv1;
        uint32_t h0 = packbf(a0, a1);
        uint32_t l0 = packbf(a0 - lo_f(h0), a1 - hi_f(h0));
        uint32_t h1 = packbf(b0, b1);
        uint32_t l1 = packbf(b0 - lo_f(h1), b1 - hi_f(h1));
        *reinterpret_cast<uint32_t*>(yh + (size_t)row0 * C_DIM + col) = h0;
        *reinterpret_cast<uint32_t*>(yl + (size_t)row0 * C_DIM + col) = l0;
        *reinterpret_cast<uint32_t*>(yh + (size_t)row1 * C_DIM + col) = h1;
        *reinterpret_cast<uint32_t*>(yl + (size_t)row1 * C_DIM + col) = l1;
    }
}

// ---------------------------------------------------------------------------
// Launch
// ---------------------------------------------------------------------------
extern "C" void kernel_launch(void* const* d_in, const int* in_sizes, int n_in,
                              void* d_out, int out_size)
{
    (void)in_sizes; (void)n_in; (void)out_size;
    const float* x      = (const float*)d_in[0];
    const float* W_qkv  = (const float*)d_in[2];
    const float* b_qkv  = (const float*)d_in[3];
    const float* W_proj = (const float*)d_in[4];
    const float* b_proj = (const float*)d_in[5];
    float* out = (float*)d_out;

    __nv_bfloat16 *xh, *xl, *qkvh, *qkvl, *yh, *yl, *wqh, *wql, *wph, *wpl;
    cudaGetSymbolAddress((void**)&xh, g_xh);
    cudaGetSymbolAddress((void**)&xl, g_xl);
    cudaGetSymbolAddress((void**)&qkvh, g_qkvh);
    cudaGetSymbolAddress((void**)&qkvl, g_qkvl);
    cudaGetSymbolAddress((void**)&yh, g_yh);
    cudaGetSymbolAddress((void**)&yl, g_yl);
    cudaGetSymbolAddress((void**)&wqh, g_wqh);
    cudaGetSymbolAddress((void**)&wql, g_wql);
    cudaGetSymbolAddress((void**)&wph, g_wph);
    cudaGetSymbolAddress((void**)&wpl, g_wpl);

    cudaFuncSetAttribute(gemm_mma,
                         cudaFuncAttributeMaxDynamicSharedMemorySize, GEMM_SMEM);
    cudaFuncSetAttribute(attn_mma,
                         cudaFuncAttributeMaxDynamicSharedMemorySize, ATT_SMEM);

    // 0) prep: weight transpose+split, input split
    transpose_split<<<dim3(QKV3 / 32, C_DIM / 32), 256>>>(
        W_qkv, wqh, wql, C_DIM, QKV3);
    transpose_split<<<dim3(C_DIM / 32, C_DIM / 32), 256>>>(
        W_proj, wph, wpl, C_DIM, C_DIM);
    split_f32<<<(T_SEQ * C_DIM / 4 + 255) / 256, 256>>>(
        x, xh, xl, T_SEQ * C_DIM / 4);

    // 1) qkv = x @ W_qkv + b_qkv -> bf16 hi/lo, Q cols pre-scaled by 0.125
    gemm_mma<<<dim3(QKV3 / 128, T_SEQ / 128), 256, GEMM_SMEM>>>(
        xh, xl, wqh, wql, b_qkv, nullptr, qkvh, qkvl, T_SEQ, QKV3, C_DIM, 1);

    // 2) y = causal_attention(qkv) -> bf16 hi/lo
    attn_mma<<<dim3(T_SEQ / 128, NHEAD), 256, ATT_SMEM>>>(qkvh, qkvl, yh, yl);

    // 3) out = y @ W_proj + b_proj (fp32)
    gemm_mma<<<dim3(C_DIM / 128, T_SEQ / 128), 256, GEMM_SMEM>>>(
        yh, yl, wph, wpl, b_proj, out, nullptr, nullptr, T_SEQ, C_DIM, C_DIM, 0);
}

// round 9
// speedup vs baseline: 3.7906x; 1.0537x over previous
#include <cuda_runtime.h>
#include <cuda_bf16.h>
#include <math.h>
#include <stdint.h>

// Problem constants
#define T_SEQ 4096
#define C_DIM 768
#define NHEAD 12
#define HDIM  64
#define QKV3  (3 * C_DIM)

// ---------------------------------------------------------------------------
// Scratch (allocation-guard-safe device globals) — all bf16 hi/lo split pairs
// ---------------------------------------------------------------------------
__device__ __nv_bfloat16 g_xh[(size_t)T_SEQ * C_DIM];
__device__ __nv_bfloat16 g_xl[(size_t)T_SEQ * C_DIM];
__device__ __nv_bfloat16 g_qkvh[(size_t)T_SEQ * QKV3];
__device__ __nv_bfloat16 g_qkvl[(size_t)T_SEQ * QKV3];
__device__ __nv_bfloat16 g_yh[(size_t)T_SEQ * C_DIM];
__device__ __nv_bfloat16 g_yl[(size_t)T_SEQ * C_DIM];
__device__ __nv_bfloat16 g_wqh[(size_t)QKV3 * C_DIM];   // W_qkv^T [3C][C]
__device__ __nv_bfloat16 g_wql[(size_t)QKV3 * C_DIM];
__device__ __nv_bfloat16 g_wph[(size_t)C_DIM * C_DIM];  // W_proj^T [C][C]
__device__ __nv_bfloat16 g_wpl[(size_t)C_DIM * C_DIM];

// ---------------------------------------------------------------------------
// MMA / ldmatrix / cp.async helpers (sm_80+ PTX; assembles on plain sm_103)
// ---------------------------------------------------------------------------
__device__ __forceinline__ uint32_t smem_u32(const void* p) {
    uint32_t a;
    asm("{ .reg .u64 t; cvta.to.shared.u64 t, %1; cvt.u32.u64 %0, t; }"
        : "=r"(a) : "l"(p));
    return a;
}
__device__ __forceinline__ void mma_bf16(float* c, const uint32_t* a,
                                         const uint32_t* b) {
    asm volatile(
        "mma.sync.aligned.m16n8k16.row.col.f32.bf16.bf16.f32 "
        "{%0,%1,%2,%3}, {%4,%5,%6,%7}, {%8,%9}, {%0,%1,%2,%3};"
        : "+f"(c[0]), "+f"(c[1]), "+f"(c[2]), "+f"(c[3])
        : "r"(a[0]), "r"(a[1]), "r"(a[2]), "r"(a[3]), "r"(b[0]), "r"(b[1]));
}
__device__ __forceinline__ void ldsm_x4(uint32_t* r, uint32_t a) {
    asm volatile("ldmatrix.sync.aligned.m8n8.x4.shared.b16 {%0,%1,%2,%3}, [%4];"
                 : "=r"(r[0]), "=r"(r[1]), "=r"(r[2]), "=r"(r[3]) : "r"(a));
}
__device__ __forceinline__ void ldsm_x4_t(uint32_t* r, uint32_t a) {
    asm volatile("ldmatrix.sync.aligned.m8n8.x4.trans.shared.b16 {%0,%1,%2,%3}, [%4];"
                 : "=r"(r[0]), "=r"(r[1]), "=r"(r[2]), "=r"(r[3]) : "r"(a));
}
__device__ __forceinline__ void cp16(uint32_t dst, const void* src) {
    asm volatile("cp.async.cg.shared.global [%0], [%1], 16;"
                 :: "r"(dst), "l"(src));
}
#define CP_COMMIT() asm volatile("cp.async.commit_group;" ::: "memory")
#define CP_WAIT1()  asm volatile("cp.async.wait_group 1;" ::: "memory")
#define CP_WAIT0()  asm volatile("cp.async.wait_group 0;" ::: "memory")

// pack two f32 -> bf16x2 (lo -> low half, hi -> high half)
__device__ __forceinline__ uint32_t packbf(float lo, float hi) {
    uint32_t d;
    asm("cvt.rn.bf16x2.f32 %0, %1, %2;" : "=r"(d) : "f"(hi), "f"(lo));
    return d;
}
__device__ __forceinline__ float lo_f(uint32_t u) { return __uint_as_float(u << 16); }
__device__ __forceinline__ float hi_f(uint32_t u) { return __uint_as_float(u & 0xffff0000u); }
__device__ __forceinline__ float ex2f(float x) {
    float y;
    asm("ex2.approx.f32 %0, %1;" : "=f"(y) : "f"(x));
    return y;
}

// byte offset into a [128][64]-bf16 tile with chunk-XOR swizzle (16B chunks)
__device__ __forceinline__ uint32_t sw_off(int row, int chunk) {
    return (uint32_t)((row << 7) + (((chunk ^ row) & 7) << 4) + ((chunk & ~7) << 4));
}

// ---------------------------------------------------------------------------
// Prep: fp32 -> bf16 hi/lo split (float4 granularity)
// ---------------------------------------------------------------------------
__global__ __launch_bounds__(256) void split_f32(
    const float* __restrict__ X, __nv_bfloat16* __restrict__ Xh,
    __nv_bfloat16* __restrict__ Xl, int n4)
{
    int i = blockIdx.x * 256 + threadIdx.x;
    if (i >= n4) return;
    float4 x = reinterpret_cast<const float4*>(X)[i];
    uint32_t h0 = packbf(x.x, x.y);
    uint32_t h1 = packbf(x.z, x.w);
    uint32_t l0 = packbf(x.x - lo_f(h0), x.y - hi_f(h0));
    uint32_t l1 = packbf(x.z - lo_f(h1), x.w - hi_f(h1));
    reinterpret_cast<uint2*>(Xh)[i] = make_uint2(h0, h1);
    reinterpret_cast<uint2*>(Xl)[i] = make_uint2(l0, l1);
}

// ---------------------------------------------------------------------------
// Prep: W[K][N] -> Wt hi/lo [N][K]
// ---------------------------------------------------------------------------
__global__ __launch_bounds__(256) void transpose_split(
    const float* __restrict__ W, __nv_bfloat16* __restrict__ Th,
    __nv_bfloat16* __restrict__ Tl, int K, int N)
{
    __shared__ float tile[32][33];
    const int tx = threadIdx.x & 31;
    const int ty = threadIdx.x >> 5;
    const int n0 = blockIdx.x * 32;
    const int k0 = blockIdx.y * 32;
#pragma unroll
    for (int i = 0; i < 4; i++)
        tile[ty + 8 * i][tx] = W[(size_t)(k0 + ty + 8 * i) * N + n0 + tx];
    __syncthreads();
#pragma unroll
    for (int i = 0; i < 4; i++) {
        const float v = tile[tx][ty + 8 * i];
        const float h = __bfloat162float(__float2bfloat16_rn(v));
        const size_t o = (size_t)(n0 + ty + 8 * i) * K + k0 + tx;
        Th[o] = __float2bfloat16_rn(h);
        Tl[o] = __float2bfloat16_rn(v - h);
    }
}

// ---------------------------------------------------------------------------
// Split-bf16 HMMA GEMM with 3-stage cp.async pipeline (1 barrier/iter).
// C[M,N] = (Ah+Al)[M,K] @ ((Bh+Bl)[N,K])^T + bias
// CTA 128x128, k-chunk 64, 8 warps (4 m-strips x 2 n-strips), warp tile 32x64.
// mode=1: bf16 hi/lo out, cols<C_DIM scaled by 0.125*log2(e) (Q, exp2 softmax).
// mode=0: fp32 out.
// ---------------------------------------------------------------------------
#define GEMM_SMEM (3 * 4 * 16384)
#define QSCALE 0.18033688011112042f   // 0.125 * log2(e)

__global__ __launch_bounds__(256) void gemm_mma(
    const __nv_bfloat16* __restrict__ Ah, const __nv_bfloat16* __restrict__ Al,
    const __nv_bfloat16* __restrict__ Bh, const __nv_bfloat16* __restrict__ Bl,
    const float* __restrict__ bias, float* __restrict__ Cf,
    __nv_bfloat16* __restrict__ Ch, __nv_bfloat16* __restrict__ Cl,
    int M, int N, int K, int mode)
{
    extern __shared__ char smb[];
    const uint32_t ubase = smem_u32(smb);

    const int tid = threadIdx.x;
    const int w = tid >> 5, lane = tid & 31;
    const int g = lane >> 2, t = lane & 3;
    const int wm = w & 3, wn = w >> 2;
    const int by = blockIdx.y, bx = blockIdx.x;

    float acc[2][8][4];
#pragma unroll
    for (int mi = 0; mi < 2; mi++)
#pragma unroll
        for (int nb = 0; nb < 8; nb++)
#pragma unroll
            for (int c = 0; c < 4; c++) acc[mi][nb][c] = 0.0f;

    const int a_row = (lane & 15);
    const int a_chs = (lane >> 4);
    const int b_row = (lane & 7) + ((lane >> 4) << 3);
    const int b_chs = (lane >> 3) & 1;

    const int NI = K / 64;

    auto load_stage = [&](int st, int k0) {
        const uint32_t ub = ubase + st * 65536;
#pragma unroll
        for (int j = 0; j < 4; j++) {
            const int i = tid + 256 * j;
            const int row = i >> 3, ch = i & 7;
            const size_t ga = (size_t)(by * 128 + row) * K + k0 + ch * 8;
            const size_t gb = (size_t)(bx * 128 + row) * K + k0 + ch * 8;
            const uint32_t so = sw_off(row, ch);
            cp16(ub + so, Ah + ga);
            cp16(ub + 16384 + so, Al + ga);
            cp16(ub + 32768 + so, Bh + gb);
            cp16(ub + 49152 + so, Bl + gb);
        }
    };

    load_stage(0, 0);
    CP_COMMIT();
    load_stage(1, 64);
    CP_COMMIT();

    for (int it = 0; it < NI; it++) {
        const int st = it % 3;
        if (it + 1 < NI) CP_WAIT1(); else CP_WAIT0();
        __syncthreads();

        const uint32_t uAh = ubase + st * 65536;
        const uint32_t uAl = uAh + 16384;
        const uint32_t uBh = uAh + 32768;
        const uint32_t uBl = uAh + 49152;

#pragma unroll
        for (int ks = 0; ks < 4; ks++) {
            uint32_t ah[2][4], al[2][4];
#pragma unroll
            for (int mi = 0; mi < 2; mi++) {
                const uint32_t so = sw_off(wm * 32 + mi * 16 + a_row, 2 * ks + a_chs);
                ldsm_x4(ah[mi], uAh + so);
                ldsm_x4(al[mi], uAl + so);
            }
#pragma unroll
            for (int nb = 0; nb < 8; nb += 2) {
                uint32_t bh4[4], bl4[4];
                const uint32_t so = sw_off(wn * 64 + nb * 8 + b_row, 2 * ks + b_chs);
                ldsm_x4(bh4, uBh + so);
                ldsm_x4(bl4, uBl + so);
#pragma unroll
                for (int mi = 0; mi < 2; mi++) {
                    mma_bf16(acc[mi][nb], ah[mi], bh4);
                    mma_bf16(acc[mi][nb], al[mi], bh4);
                    mma_bf16(acc[mi][nb], ah[mi], bl4);
                    mma_bf16(acc[mi][nb + 1], ah[mi], bh4 + 2);
                    mma_bf16(acc[mi][nb + 1], al[mi], bh4 + 2);
                    mma_bf16(acc[mi][nb + 1], ah[mi], bl4 + 2);
                }
            }
        }

        if (it + 2 < NI) {
            load_stage((it + 2) % 3, (it + 2) * 64);
            CP_COMMIT();
        }
    }

    // Epilogue
#pragma unroll
    for (int mi = 0; mi < 2; mi++) {
#pragma unroll
        for (int nb = 0; nb < 8; nb++) {
            const int row = by * 128 + wm * 32 + mi * 16 + g;
            const int col = bx * 128 + wn * 64 + nb * 8 + t * 2;
            const float2 bb = *reinterpret_cast<const float2*>(bias + col);
            float v0 = acc[mi][nb][0] + bb.x;
            float v1 = acc[mi][nb][1] + bb.y;
            float v2 = acc[mi][nb][2] + bb.x;
            float v3 = acc[mi][nb][3] + bb.y;
            if (mode) {
                const float sc = (col < C_DIM) ? QSCALE : 1.0f;  // Q -> log2 domain
                v0 *= sc; v1 *= sc; v2 *= sc; v3 *= sc;
                uint32_t h0 = packbf(v0, v1);
                uint32_t l0 = packbf(v0 - lo_f(h0), v1 - hi_f(h0));
                uint32_t h1 = packbf(v2, v3);
                uint32_t l1 = packbf(v2 - lo_f(h1), v3 - hi_f(h1));
                *reinterpret_cast<uint32_t*>(Ch + (size_t)row * N + col) = h0;
                *reinterpret_cast<uint32_t*>(Cl + (size_t)row * N + col) = l0;
                *reinterpret_cast<uint32_t*>(Ch + (size_t)(row + 8) * N + col) = h1;
                *reinterpret_cast<uint32_t*>(Cl + (size_t)(row + 8) * N + col) = l1;
            } else {
                *reinterpret_cast<float2*>(Cf + (size_t)row * N + col) =
                    make_float2(v0, v1);
                *reinterpret_cast<float2*>(Cf + (size_t)(row + 8) * N + col) =
                    make_float2(v2, v3);
            }
        }
    }
}

// ---------------------------------------------------------------------------
// Flash attention, split-bf16 HMMA, 3-stage cp.async K/V pipeline
// (1 barrier/iter), softmax in exp2 domain (Q pre-scaled by log2e/8).
// CTA = 128 q-rows x 1 head; 8 warps x 16 q-rows. P in registers.
// SMEM: Q (32KB) + 3 stages x 64KB = 224KB.
// ---------------------------------------------------------------------------
#define ATT_SMEM (2 * 16384 + 3 * 4 * 16384)

__global__ __launch_bounds__(256, 1) void attn_mma(
    const __nv_bfloat16* __restrict__ qkvh, const __nv_bfloat16* __restrict__ qkvl,
    __nv_bfloat16* __restrict__ yh, __nv_bfloat16* __restrict__ yl)
{
    extern __shared__ char smb[];
    const uint32_t uQh = smem_u32(smb);
    const uint32_t uQl = uQh + 16384;
    const uint32_t uKV = uQh + 32768;   // stage s: +s*65536

    const int qb = 31 - (int)blockIdx.x;   // long CTAs first
    const int h = blockIdx.y;
    const int tid = threadIdx.x;
    const int w = tid >> 5, lane = tid & 31;
    const int g = lane >> 2, t = lane & 3;
    const int r0 = w * 16;

    const size_t qoff = (size_t)h * HDIM;
    const size_t koff = C_DIM + (size_t)h * HDIM;
    const size_t voff = 2 * C_DIM + (size_t)h * HDIM;

    auto load_kv = [&](int st, int kb) {
        const uint32_t ub = uKV + st * 65536;
#pragma unroll
        for (int j = 0; j < 4; j++) {
            const int i = tid + 256 * j;
            const int row = i >> 3, ch = i & 7;
            const size_t gk = (size_t)(kb * 128 + row) * QKV3 + koff + ch * 8;
            const size_t gv = (size_t)(kb * 128 + row) * QKV3 + voff + ch * 8;
            const uint32_t so = sw_off(row, ch);
            cp16(ub + so, qkvh + gk);
            cp16(ub + 16384 + so, qkvl + gk);
            cp16(ub + 32768 + so, qkvh + gv);
            cp16(ub + 49152 + so, qkvl + gv);
        }
    };

    // Prefetch K/V blocks 0 and 1, then load Q (regular STS) while DMA drains
    load_kv(0, 0);
    CP_COMMIT();
    if (qb >= 1) {
        load_kv(1, 1);
        CP_COMMIT();
    }
#pragma unroll 4
    for (int i = tid; i < 1024; i += 256) {
        const int row = i >> 3, ch = i & 7;
        const size_t gq = (size_t)(qb * 128 + row) * QKV3 + qoff + ch * 8;
        const uint32_t so = sw_off(row, ch);
        *reinterpret_cast<uint4*>(smb + so) =
            *reinterpret_cast<const uint4*>(qkvh + gq);
        *reinterpret_cast<uint4*>(smb + 16384 + so) =
            *reinterpret_cast<const uint4*>(qkvl + gq);
    }
    __syncthreads();

    // Q fragments (registers for the whole kernel); Q already in log2 domain
    uint32_t qfh[4][4], qfl[4][4];
    {
        const int arow = r0 + (lane & 15);
        const int achs = (lane >> 4);
#pragma unroll
        for (int ks = 0; ks < 4; ks++) {
            ldsm_x4(qfh[ks], uQh + sw_off(arow, 2 * ks + achs));
            ldsm_x4(qfl[ks], uQl + sw_off(arow, 2 * ks + achs));
        }
    }

    float o[8][4];
#pragma unroll
    for (int nb = 0; nb < 8; nb++)
#pragma unroll
        for (int c = 0; c < 4; c++) o[nb][c] = 0.0f;
    float m0r = -INFINITY, m1r = -INFINITY, l0r = 0.0f, l1r = 0.0f;

    const int b_row = (lane & 7) + ((lane >> 4) << 3);
    const int b_chs = (lane >> 3) & 1;
    const int v_row = (lane & 7) + (((lane >> 3) & 1) << 3);
    const int v_chs = (lane >> 4);

    for (int kb = 0; kb <= qb; kb++) {
        const int st = kb % 3;
        if (kb < qb) CP_WAIT1(); else CP_WAIT0();
        __syncthreads();

        const uint32_t uKh = uKV + st * 65536;
        const uint32_t uKl = uKh + 16384;
        const uint32_t uVh = uKh + 32768;
        const uint32_t uVl = uKh + 49152;

        // ---- S = Q @ K^T (log2 domain; 16 n-blocks of 8 keys) ----
        float s[16][4];
#pragma unroll
        for (int nb = 0; nb < 16; nb++)
#pragma unroll
            for (int c = 0; c < 4; c++) s[nb][c] = 0.0f;

#pragma unroll
        for (int nb = 0; nb < 16; nb += 2) {
#pragma unroll
            for (int ks = 0; ks < 4; ks++) {
                uint32_t kh4[4], kl4[4];
                const uint32_t so = sw_off(nb * 8 + b_row, 2 * ks + b_chs);
                ldsm_x4(kh4, uKh + so);
                ldsm_x4(kl4, uKl + so);
                mma_bf16(s[nb], qfh[ks], kh4);
                mma_bf16(s[nb], qfl[ks], kh4);
                mma_bf16(s[nb], qfh[ks], kl4);
                mma_bf16(s[nb + 1], qfh[ks], kh4 + 2);
                mma_bf16(s[nb + 1], qfl[ks], kh4 + 2);
                mma_bf16(s[nb + 1], qfh[ks], kl4 + 2);
            }
        }

        // ---- causal mask on the diagonal block ----
        if (kb == qb) {
            const int ra = r0 + g, rb = r0 + g + 8;
#pragma unroll
            for (int nb = 0; nb < 16; nb++) {
                const int cb = nb * 8 + t * 2;
                if (cb > ra)     s[nb][0] = -1e30f;
                if (cb + 1 > ra) s[nb][1] = -1e30f;
                if (cb > rb)     s[nb][2] = -1e30f;
                if (cb + 1 > rb) s[nb][3] = -1e30f;
            }
        }

        // ---- online softmax in exp2 domain (rows g / g+8) ----
        float mx0 = -INFINITY, mx1 = -INFINITY;
#pragma unroll
        for (int nb = 0; nb < 16; nb++) {
            mx0 = fmaxf(mx0, fmaxf(s[nb][0], s[nb][1]));
            mx1 = fmaxf(mx1, fmaxf(s[nb][2], s[nb][3]));
        }
        mx0 = fmaxf(mx0, __shfl_xor_sync(0xffffffffu, mx0, 1));
        mx0 = fmaxf(mx0, __shfl_xor_sync(0xffffffffu, mx0, 2));
        mx1 = fmaxf(mx1, __shfl_xor_sync(0xffffffffu, mx1, 1));
        mx1 = fmaxf(mx1, __shfl_xor_sync(0xffffffffu, mx1, 2));
        const float mn0 = fmaxf(m0r, mx0);
        const float mn1 = fmaxf(m1r, mx1);
        const float c0 = ex2f(m0r - mn0);
        const float c1 = ex2f(m1r - mn1);
        float sum0 = 0.0f, sum1 = 0.0f;
#pragma unroll
        for (int nb = 0; nb < 16; nb++) {
            s[nb][0] = ex2f(s[nb][0] - mn0);
            s[nb][1] = ex2f(s[nb][1] - mn0);
            s[nb][2] = ex2f(s[nb][2] - mn1);
            s[nb][3] = ex2f(s[nb][3] - mn1);
            sum0 += s[nb][0] + s[nb][1];
            sum1 += s[nb][2] + s[nb][3];
        }
        sum0 += __shfl_xor_sync(0xffffffffu, sum0, 1);
        sum0 += __shfl_xor_sync(0xffffffffu, sum0, 2);
        sum1 += __shfl_xor_sync(0xffffffffu, sum1, 1);
        sum1 += __shfl_xor_sync(0xffffffffu, sum1, 2);
        l0r = l0r * c0 + sum0;
        l1r = l1r * c1 + sum1;
        m0r = mn0; m1r = mn1;
#pragma unroll
        for (int nb = 0; nb < 8; nb++) {
            o[nb][0] *= c0; o[nb][1] *= c0;
            o[nb][2] *= c1; o[nb][3] *= c1;
        }

        // ---- O += P @ V (P refragmented from S C-frags, split hi/lo) ----
#pragma unroll
        for (int kk = 0; kk < 8; kk++) {
            uint32_t ph[4], pl[4];
            ph[0] = packbf(s[2 * kk][0], s[2 * kk][1]);
            pl[0] = packbf(s[2 * kk][0] - lo_f(ph[0]), s[2 * kk][1] - hi_f(ph[0]));
            ph[1] = packbf(s[2 * kk][2], s[2 * kk][3]);
            pl[1] = packbf(s[2 * kk][2] - lo_f(ph[1]), s[2 * kk][3] - hi_f(ph[1]));
            ph[2] = packbf(s[2 * kk + 1][0], s[2 * kk + 1][1]);
            pl[2] = packbf(s[2 * kk + 1][0] - lo_f(ph[2]), s[2 * kk + 1][1] - hi_f(ph[2]));
            ph[3] = packbf(s[2 * kk + 1][2], s[2 * kk + 1][3]);
            pl[3] = packbf(s[2 * kk + 1][2] - lo_f(ph[3]), s[2 * kk + 1][3] - hi_f(ph[3]));
#pragma unroll
            for (int nb = 0; nb < 8; nb += 2) {
                uint32_t vh4[4], vl4[4];
                const uint32_t so = sw_off(kk * 16 + v_row, nb + v_chs);
                ldsm_x4_t(vh4, uVh + so);
                ldsm_x4_t(vl4, uVl + so);
                mma_bf16(o[nb], ph, vh4);
                mma_bf16(o[nb], pl, vh4);
                mma_bf16(o[nb], ph, vl4);
                mma_bf16(o[nb + 1], ph, vh4 + 2);
                mma_bf16(o[nb + 1], pl, vh4 + 2);
                mma_bf16(o[nb + 1], ph, vl4 + 2);
            }
        }

        // prefetch K/V for kb+2 into the stage last read at iter kb-1
        if (kb + 2 <= qb) {
            load_kv((kb + 2) % 3, kb + 2);
            CP_COMMIT();
        }
    }

    // ---- normalize and write y (bf16 hi/lo split) ----
    const float inv0 = 1.0f / l0r;
    const float inv1 = 1.0f / l1r;
    const int row0 = qb * 128 + r0 + g;
    const int row1 = row0 + 8;
#pragma unroll
    for (int nb = 0; nb < 8; nb++) {
        const int col = h * HDIM + nb * 8 + t * 2;
        float a0 = o[nb][0] * inv0, a1 = o[nb][1] * inv0;
        float b0 = o[nb][2] * inv1, b1 = o[nb][3] * inv1;
        uint32_t h0 = packbf(a0, a1);
        uint32_t l0 = packbf(a0 - lo_f(h0), a1 - hi_f(h0));
        uint32_t h1 = packbf(b0, b1);
        uint32_t l1 = packbf(b0 - lo_f(h1), b1 - hi_f(h1));
        *reinterpret_cast<uint32_t*>(yh + (size_t)row0 * C_DIM + col) = h0;
        *reinterpret_cast<uint32_t*>(yl + (size_t)row0 * C_DIM + col) = l0;
        *reinterpret_cast<uint32_t*>(yh + (size_t)row1 * C_DIM + col) = h1;
        *reinterpret_cast<uint32_t*>(yl + (size_t)row1 * C_DIM + col) = l1;
    }
}

// ---------------------------------------------------------------------------
// Launch
// ---------------------------------------------------------------------------
extern "C" void kernel_launch(void* const* d_in, const int* in_sizes, int n_in,
                              void* d_out, int out_size)
{
    (void)in_sizes; (void)n_in; (void)out_size;
    const float* x      = (const float*)d_in[0];
    const float* W_qkv  = (const float*)d_in[2];
    const float* b_qkv  = (const float*)d_in[3];
    const float* W_proj = (const float*)d_in[4];
    const float* b_proj = (const float*)d_in[5];
    float* out = (float*)d_out;

    __nv_bfloat16 *xh, *xl, *qkvh, *qkvl, *yh, *yl, *wqh, *wql, *wph, *wpl;
    cudaGetSymbolAddress((void**)&xh, g_xh);
    cudaGetSymbolAddress((void**)&xl, g_xl);
    cudaGetSymbolAddress((void**)&qkvh, g_qkvh);
    cudaGetSymbolAddress((void**)&qkvl, g_qkvl);
    cudaGetSymbolAddress((void**)&yh, g_yh);
    cudaGetSymbolAddress((void**)&yl, g_yl);
    cudaGetSymbolAddress((void**)&wqh, g_wqh);
    cudaGetSymbolAddress((void**)&wql, g_wql);
    cudaGetSymbolAddress((void**)&wph, g_wph);
    cudaGetSymbolAddress((void**)&wpl, g_wpl);

    cudaFuncSetAttribute(gemm_mma,
                         cudaFuncAttributeMaxDynamicSharedMemorySize, GEMM_SMEM);
    cudaFuncSetAttribute(attn_mma,
                         cudaFuncAttributeMaxDynamicSharedMemorySize, ATT_SMEM);

    // 0) prep: weight transpose+split, input split
    transpose_split<<<dim3(QKV3 / 32, C_DIM / 32), 256>>>(
        W_qkv, wqh, wql, C_DIM, QKV3);
    transpose_split<<<dim3(C_DIM / 32, C_DIM / 32), 256>>>(
        W_proj, wph, wpl, C_DIM, C_DIM);
    split_f32<<<(T_SEQ * C_DIM / 4 + 255) / 256, 256>>>(
        x, xh, xl, T_SEQ * C_DIM / 4);

    // 1) qkv = x @ W_qkv + b_qkv -> bf16 hi/lo, Q cols scaled to log2 domain
    gemm_mma<<<dim3(QKV3 / 128, T_SEQ / 128), 256, GEMM_SMEM>>>(
        xh, xl, wqh, wql, b_qkv, nullptr, qkvh, qkvl, T_SEQ, QKV3, C_DIM, 1);

    // 2) y = causal_attention(qkv) -> bf16 hi/lo
    attn_mma<<<dim3(T_SEQ / 128, NHEAD), 256, ATT_SMEM>>>(qkvh, qkvl, yh, yl);

    // 3) out = y @ W_proj + b_proj (fp32)
    gemm_mma<<<dim3(C_DIM / 128, T_SEQ / 128), 256, GEMM_SMEM>>>(
        yh, yl, wph, wpl, b_proj, out, nullptr, nullptr, T_SEQ, C_DIM, C_DIM, 0);
}

// round 10
// speedup vs baseline: 4.0314x; 1.0635x over previous
#include <cuda_runtime.h>
#include <cuda_bf16.h>
#include <cuda_fp16.h>
#include <math.h>
#include <stdint.h>

// Problem constants
#define T_SEQ 4096
#define C_DIM 768
#define NHEAD 12
#define HDIM  64
#define QKV3  (3 * C_DIM)

// ---------------------------------------------------------------------------
// Scratch (allocation-guard-safe device globals) — bf16 hi/lo split pairs
// (V region of qkv holds fp16 hi/lo instead; same storage size)
// ---------------------------------------------------------------------------
__device__ __nv_bfloat16 g_xh[(size_t)T_SEQ * C_DIM];
__device__ __nv_bfloat16 g_xl[(size_t)T_SEQ * C_DIM];
__device__ __nv_bfloat16 g_qkvh[(size_t)T_SEQ * QKV3];
__device__ __nv_bfloat16 g_qkvl[(size_t)T_SEQ * QKV3];
__device__ __nv_bfloat16 g_yh[(size_t)T_SEQ * C_DIM];
__device__ __nv_bfloat16 g_yl[(size_t)T_SEQ * C_DIM];
__device__ __nv_bfloat16 g_wqh[(size_t)QKV3 * C_DIM];   // W_qkv^T [3C][C]
__device__ __nv_bfloat16 g_wql[(size_t)QKV3 * C_DIM];
__device__ __nv_bfloat16 g_wph[(size_t)C_DIM * C_DIM];  // W_proj^T [C][C]
__device__ __nv_bfloat16 g_wpl[(size_t)C_DIM * C_DIM];

// ---------------------------------------------------------------------------
// MMA / ldmatrix / cp.async helpers (sm_80+ PTX; assembles on plain sm_103)
// ---------------------------------------------------------------------------
__device__ __forceinline__ uint32_t smem_u32(const void* p) {
    uint32_t a;
    asm("{ .reg .u64 t; cvta.to.shared.u64 t, %1; cvt.u32.u64 %0, t; }"
        : "=r"(a) : "l"(p));
    return a;
}
__device__ __forceinline__ void mma_bf16(float* c, const uint32_t* a,
                                         const uint32_t* b) {
    asm volatile(
        "mma.sync.aligned.m16n8k16.row.col.f32.bf16.bf16.f32 "
        "{%0,%1,%2,%3}, {%4,%5,%6,%7}, {%8,%9}, {%0,%1,%2,%3};"
        : "+f"(c[0]), "+f"(c[1]), "+f"(c[2]), "+f"(c[3])
        : "r"(a[0]), "r"(a[1]), "r"(a[2]), "r"(a[3]), "r"(b[0]), "r"(b[1]));
}
__device__ __forceinline__ void mma_f16(float* c, const uint32_t* a,
                                        const uint32_t* b) {
    asm volatile(
        "mma.sync.aligned.m16n8k16.row.col.f32.f16.f16.f32 "
        "{%0,%1,%2,%3}, {%4,%5,%6,%7}, {%8,%9}, {%0,%1,%2,%3};"
        : "+f"(c[0]), "+f"(c[1]), "+f"(c[2]), "+f"(c[3])
        : "r"(a[0]), "r"(a[1]), "r"(a[2]), "r"(a[3]), "r"(b[0]), "r"(b[1]));
}
__device__ __forceinline__ void ldsm_x4(uint32_t* r, uint32_t a) {
    asm volatile("ldmatrix.sync.aligned.m8n8.x4.shared.b16 {%0,%1,%2,%3}, [%4];"
                 : "=r"(r[0]), "=r"(r[1]), "=r"(r[2]), "=r"(r[3]) : "r"(a));
}
__device__ __forceinline__ void ldsm_x4_t(uint32_t* r, uint32_t a) {
    asm volatile("ldmatrix.sync.aligned.m8n8.x4.trans.shared.b16 {%0,%1,%2,%3}, [%4];"
                 : "=r"(r[0]), "=r"(r[1]), "=r"(r[2]), "=r"(r[3]) : "r"(a));
}
__device__ __forceinline__ void cp16(uint32_t dst, const void* src) {
    asm volatile("cp.async.cg.shared.global [%0], [%1], 16;"
                 :: "r"(dst), "l"(src));
}
#define CP_COMMIT() asm volatile("cp.async.commit_group;" ::: "memory")
#define CP_WAIT1()  asm volatile("cp.async.wait_group 1;" ::: "memory")
#define CP_WAIT0()  asm volatile("cp.async.wait_group 0;" ::: "memory")

// pack two f32 -> bf16x2 / f16x2 (first arg -> low half)
__device__ __forceinline__ uint32_t packbf(float lo, float hi) {
    uint32_t d;
    asm("cvt.rn.bf16x2.f32 %0, %1, %2;" : "=r"(d) : "f"(hi), "f"(lo));
    return d;
}
__device__ __forceinline__ uint32_t packhf(float lo, float hi) {
    uint32_t d;
    asm("cvt.rn.f16x2.f32 %0, %1, %2;" : "=r"(d) : "f"(hi), "f"(lo));
    return d;
}
__device__ __forceinline__ float lo_f(uint32_t u) { return __uint_as_float(u << 16); }
__device__ __forceinline__ float hi_f(uint32_t u) { return __uint_as_float(u & 0xffff0000u); }
__device__ __forceinline__ float lo_h(uint32_t u) {
    __half2 h = *reinterpret_cast<__half2*>(&u);
    return __half2float(h.x);
}
__device__ __forceinline__ float hi_h(uint32_t u) {
    __half2 h = *reinterpret_cast<__half2*>(&u);
    return __half2float(h.y);
}
__device__ __forceinline__ float ex2f(float x) {
    float y;
    asm("ex2.approx.f32 %0, %1;" : "=f"(y) : "f"(x));
    return y;
}

// byte offset into a [128][64]-bf16 tile with chunk-XOR swizzle (16B chunks)
__device__ __forceinline__ uint32_t sw_off(int row, int chunk) {
    return (uint32_t)((row << 7) + (((chunk ^ row) & 7) << 4) + ((chunk & ~7) << 4));
}

// ---------------------------------------------------------------------------
// Prep: fp32 -> bf16 hi/lo split (float4 granularity)
// ---------------------------------------------------------------------------
__global__ __launch_bounds__(256) void split_f32(
    const float* __restrict__ X, __nv_bfloat16* __restrict__ Xh,
    __nv_bfloat16* __restrict__ Xl, int n4)
{
    int i = blockIdx.x * 256 + threadIdx.x;
    if (i >= n4) return;
    float4 x = reinterpret_cast<const float4*>(X)[i];
    uint32_t h0 = packbf(x.x, x.y);
    uint32_t h1 = packbf(x.z, x.w);
    uint32_t l0 = packbf(x.x - lo_f(h0), x.y - hi_f(h0));
    uint32_t l1 = packbf(x.z - lo_f(h1), x.w - hi_f(h1));
    reinterpret_cast<uint2*>(Xh)[i] = make_uint2(h0, h1);
    reinterpret_cast<uint2*>(Xl)[i] = make_uint2(l0, l1);
}

// ---------------------------------------------------------------------------
// Prep: W[K][N] -> Wt hi/lo [N][K]
// ---------------------------------------------------------------------------
__global__ __launch_bounds__(256) void transpose_split(
    const float* __restrict__ W, __nv_bfloat16* __restrict__ Th,
    __nv_bfloat16* __restrict__ Tl, int K, int N)
{
    __shared__ float tile[32][33];
    const int tx = threadIdx.x & 31;
    const int ty = threadIdx.x >> 5;
    const int n0 = blockIdx.x * 32;
    const int k0 = blockIdx.y * 32;
#pragma unroll
    for (int i = 0; i < 4; i++)
        tile[ty + 8 * i][tx] = W[(size_t)(k0 + ty + 8 * i) * N + n0 + tx];
    __syncthreads();
#pragma unroll
    for (int i = 0; i < 4; i++) {
        const float v = tile[tx][ty + 8 * i];
        const float h = __bfloat162float(__float2bfloat16_rn(v));
        const size_t o = (size_t)(n0 + ty + 8 * i) * K + k0 + tx;
        Th[o] = __float2bfloat16_rn(h);
        Tl[o] = __float2bfloat16_rn(v - h);
    }
}

// ---------------------------------------------------------------------------
// Split-bf16 HMMA GEMM with 3-stage cp.async pipeline (1 barrier/iter).
// C[M,N] = (Ah+Al)[M,K] @ ((Bh+Bl)[N,K])^T + bias
// mode=1 (QKV): bf16 hi/lo out; Q cols scaled by 0.125*log2(e);
//               V cols (>=2C) written as fp16 hi/lo (for fp16 PV in attn).
// mode=0: fp32 out.
// ---------------------------------------------------------------------------
#define GEMM_SMEM (3 * 4 * 16384)
#define QSCALE 0.18033688011112042f   // 0.125 * log2(e)

__global__ __launch_bounds__(256) void gemm_mma(
    const __nv_bfloat16* __restrict__ Ah, const __nv_bfloat16* __restrict__ Al,
    const __nv_bfloat16* __restrict__ Bh, const __nv_bfloat16* __restrict__ Bl,
    const float* __restrict__ bias, float* __restrict__ Cf,
    __nv_bfloat16* __restrict__ Ch, __nv_bfloat16* __restrict__ Cl,
    int M, int N, int K, int mode)
{
    extern __shared__ char smb[];
    const uint32_t ubase = smem_u32(smb);

    const int tid = threadIdx.x;
    const int w = tid >> 5, lane = tid & 31;
    const int g = lane >> 2, t = lane & 3;
    const int wm = w & 3, wn = w >> 2;
    const int by = blockIdx.y, bx = blockIdx.x;

    float acc[2][8][4];
#pragma unroll
    for (int mi = 0; mi < 2; mi++)
#pragma unroll
        for (int nb = 0; nb < 8; nb++)
#pragma unroll
            for (int c = 0; c < 4; c++) acc[mi][nb][c] = 0.0f;

    const int a_row = (lane & 15);
    const int a_chs = (lane >> 4);
    const int b_row = (lane & 7) + ((lane >> 4) << 3);
    const int b_chs = (lane >> 3) & 1;

    const int NI = K / 64;

    auto load_stage = [&](int st, int k0) {
        const uint32_t ub = ubase + st * 65536;
#pragma unroll
        for (int j = 0; j < 4; j++) {
            const int i = tid + 256 * j;
            const int row = i >> 3, ch = i & 7;
            const size_t ga = (size_t)(by * 128 + row) * K + k0 + ch * 8;
            const size_t gb = (size_t)(bx * 128 + row) * K + k0 + ch * 8;
            const uint32_t so = sw_off(row, ch);
            cp16(ub + so, Ah + ga);
            cp16(ub + 16384 + so, Al + ga);
            cp16(ub + 32768 + so, Bh + gb);
            cp16(ub + 49152 + so, Bl + gb);
        }
    };

    load_stage(0, 0);
    CP_COMMIT();
    load_stage(1, 64);
    CP_COMMIT();

    for (int it = 0; it < NI; it++) {
        const int st = it % 3;
        if (it + 1 < NI) CP_WAIT1(); else CP_WAIT0();
        __syncthreads();

        // prefetch it+2 into the stage last read at it-1 (ordered by barrier)
        if (it + 2 < NI) {
            load_stage((it + 2) % 3, (it + 2) * 64);
            CP_COMMIT();
        }

        const uint32_t uAh = ubase + st * 65536;
        const uint32_t uAl = uAh + 16384;
        const uint32_t uBh = uAh + 32768;
        const uint32_t uBl = uAh + 49152;

#pragma unroll
        for (int ks = 0; ks < 4; ks++) {
            uint32_t ah[2][4], al[2][4];
#pragma unroll
            for (int mi = 0; mi < 2; mi++) {
                const uint32_t so = sw_off(wm * 32 + mi * 16 + a_row, 2 * ks + a_chs);
                ldsm_x4(ah[mi], uAh + so);
                ldsm_x4(al[mi], uAl + so);
            }
#pragma unroll
            for (int nb = 0; nb < 8; nb += 2) {
                uint32_t bh4[4], bl4[4];
                const uint32_t so = sw_off(wn * 64 + nb * 8 + b_row, 2 * ks + b_chs);
                ldsm_x4(bh4, uBh + so);
                ldsm_x4(bl4, uBl + so);
#pragma unroll
                for (int mi = 0; mi < 2; mi++) {
                    mma_bf16(acc[mi][nb], ah[mi], bh4);
                    mma_bf16(acc[mi][nb], al[mi], bh4);
                    mma_bf16(acc[mi][nb], ah[mi], bl4);
                    mma_bf16(acc[mi][nb + 1], ah[mi], bh4 + 2);
                    mma_bf16(acc[mi][nb + 1], al[mi], bh4 + 2);
                    mma_bf16(acc[mi][nb + 1], ah[mi], bl4 + 2);
                }
            }
        }
    }

    // Epilogue
    const bool v_region = (mode == 1) && (bx * 128 >= 2 * C_DIM);  // V cols -> fp16
#pragma unroll
    for (int mi = 0; mi < 2; mi++) {
#pragma unroll
        for (int nb = 0; nb < 8; nb++) {
            const int row = by * 128 + wm * 32 + mi * 16 + g;
            const int col = bx * 128 + wn * 64 + nb * 8 + t * 2;
            const float2 bb = *reinterpret_cast<const float2*>(bias + col);
            float v0 = acc[mi][nb][0] + bb.x;
            float v1 = acc[mi][nb][1] + bb.y;
            float v2 = acc[mi][nb][2] + bb.x;
            float v3 = acc[mi][nb][3] + bb.y;
            if (mode) {
                uint32_t h0, l0, h1, l1;
                if (v_region) {
                    h0 = packhf(v0, v1);
                    l0 = packhf(v0 - lo_h(h0), v1 - hi_h(h0));
                    h1 = packhf(v2, v3);
                    l1 = packhf(v2 - lo_h(h1), v3 - hi_h(h1));
                } else {
                    const float sc = (col < C_DIM) ? QSCALE : 1.0f;  // Q -> log2 domain
                    v0 *= sc; v1 *= sc; v2 *= sc; v3 *= sc;
                    h0 = packbf(v0, v1);
                    l0 = packbf(v0 - lo_f(h0), v1 - hi_f(h0));
                    h1 = packbf(v2, v3);
                    l1 = packbf(v2 - lo_f(h1), v3 - hi_f(h1));
                }
                *reinterpret_cast<uint32_t*>(Ch + (size_t)row * N + col) = h0;
                *reinterpret_cast<uint32_t*>(Cl + (size_t)row * N + col) = l0;
                *reinterpret_cast<uint32_t*>(Ch + (size_t)(row + 8) * N + col) = h1;
                *reinterpret_cast<uint32_t*>(Cl + (size_t)(row + 8) * N + col) = l1;
            } else {
                *reinterpret_cast<float2*>(Cf + (size_t)row * N + col) =
                    make_float2(v0, v1);
                *reinterpret_cast<float2*>(Cf + (size_t)(row + 8) * N + col) =
                    make_float2(v2, v3);
            }
        }
    }
}

// ---------------------------------------------------------------------------
// Flash attention: S = split-bf16 3-term HMMA; PV = fp16 2-term with an
// all-ones constant B-fragment accumulating the softmax normalizer (l) as a
// 9th output block. 3-stage cp.async K/V pipeline, exp2-domain softmax.
// CTA = 128 q-rows x 1 head; 8 warps x 16 q-rows. P in registers (fp16).
// ---------------------------------------------------------------------------
#define ATT_SMEM (2 * 16384 + 3 * 4 * 16384)
#define ONES_F16X2 0x3C003C00u

__global__ __launch_bounds__(256, 1) void attn_mma(
    const __nv_bfloat16* __restrict__ qkvh, const __nv_bfloat16* __restrict__ qkvl,
    __nv_bfloat16* __restrict__ yh, __nv_bfloat16* __restrict__ yl)
{
    extern __shared__ char smb[];
    const uint32_t uQh = smem_u32(smb);
    const uint32_t uQl = uQh + 16384;
    const uint32_t uKV = uQh + 32768;   // stage s: +s*65536

    const int qb = 31 - (int)blockIdx.x;   // long CTAs first
    const int h = blockIdx.y;
    const int tid = threadIdx.x;
    const int w = tid >> 5, lane = tid & 31;
    const int g = lane >> 2, t = lane & 3;
    const int r0 = w * 16;

    const size_t qoff = (size_t)h * HDIM;
    const size_t koff = C_DIM + (size_t)h * HDIM;
    const size_t voff = 2 * C_DIM + (size_t)h * HDIM;

    auto load_kv = [&](int st, int kb) {
        const uint32_t ub = uKV + st * 65536;
#pragma unroll
        for (int j = 0; j < 4; j++) {
            const int i = tid + 256 * j;
            const int row = i >> 3, ch = i & 7;
            const size_t gk = (size_t)(kb * 128 + row) * QKV3 + koff + ch * 8;
            const size_t gv = (size_t)(kb * 128 + row) * QKV3 + voff + ch * 8;
            const uint32_t so = sw_off(row, ch);
            cp16(ub + so, qkvh + gk);
            cp16(ub + 16384 + so, qkvl + gk);
            cp16(ub + 32768 + so, qkvh + gv);
            cp16(ub + 49152 + so, qkvl + gv);
        }
    };

    // Prefetch K/V blocks 0 and 1, then load Q (regular STS) while DMA drains
    load_kv(0, 0);
    CP_COMMIT();
    if (qb >= 1) {
        load_kv(1, 1);
        CP_COMMIT();
    }
#pragma unroll 4
    for (int i = tid; i < 1024; i += 256) {
        const int row = i >> 3, ch = i & 7;
        const size_t gq = (size_t)(qb * 128 + row) * QKV3 + qoff + ch * 8;
        const uint32_t so = sw_off(row, ch);
        *reinterpret_cast<uint4*>(smb + so) =
            *reinterpret_cast<const uint4*>(qkvh + gq);
        *reinterpret_cast<uint4*>(smb + 16384 + so) =
            *reinterpret_cast<const uint4*>(qkvl + gq);
    }
    __syncthreads();

    // Q fragments (registers for the whole kernel); Q already in log2 domain
    uint32_t qfh[4][4], qfl[4][4];
    {
        const int arow = r0 + (lane & 15);
        const int achs = (lane >> 4);
#pragma unroll
        for (int ks = 0; ks < 4; ks++) {
            ldsm_x4(qfh[ks], uQh + sw_off(arow, 2 * ks + achs));
            ldsm_x4(qfl[ks], uQl + sw_off(arow, 2 * ks + achs));
        }
    }

    // o[0..7] = output dims; o[8] = softmax normalizer (ones-column block)
    float o[9][4];
#pragma unroll
    for (int nb = 0; nb < 9; nb++)
#pragma unroll
        for (int c = 0; c < 4; c++) o[nb][c] = 0.0f;
    float m0r = -INFINITY, m1r = -INFINITY;

    const uint32_t ones2[2] = { ONES_F16X2, ONES_F16X2 };

    const int b_row = (lane & 7) + ((lane >> 4) << 3);
    const int b_chs = (lane >> 3) & 1;
    const int v_row = (lane & 7) + (((lane >> 3) & 1) << 3);
    const int v_chs = (lane >> 4);

    for (int kb = 0; kb <= qb; kb++) {
        const int st = kb % 3;
        if (kb < qb) CP_WAIT1(); else CP_WAIT0();
        __syncthreads();

        // prefetch kb+2 into the stage last read at kb-1 (ordered by barrier)
        if (kb + 2 <= qb) {
            load_kv((kb + 2) % 3, kb + 2);
            CP_COMMIT();
        }

        const uint32_t uKh = uKV + st * 65536;
        const uint32_t uKl = uKh + 16384;
        const uint32_t uVh = uKh + 32768;
        const uint32_t uVl = uKh + 49152;

        // ---- S = Q @ K^T (log2 domain; 16 n-blocks of 8 keys) ----
        float s[16][4];
#pragma unroll
        for (int nb = 0; nb < 16; nb++)
#pragma unroll
            for (int c = 0; c < 4; c++) s[nb][c] = 0.0f;

#pragma unroll
        for (int nb = 0; nb < 16; nb += 2) {
#pragma unroll
            for (int ks = 0; ks < 4; ks++) {
                uint32_t kh4[4], kl4[4];
                const uint32_t so = sw_off(nb * 8 + b_row, 2 * ks + b_chs);
                ldsm_x4(kh4, uKh + so);
                ldsm_x4(kl4, uKl + so);
                mma_bf16(s[nb], qfh[ks], kh4);
                mma_bf16(s[nb], qfl[ks], kh4);
                mma_bf16(s[nb], qfh[ks], kl4);
                mma_bf16(s[nb + 1], qfh[ks], kh4 + 2);
                mma_bf16(s[nb + 1], qfl[ks], kh4 + 2);
                mma_bf16(s[nb + 1], qfh[ks], kl4 + 2);
            }
        }

        // ---- causal mask on the diagonal block ----
        if (kb == qb) {
            const int ra = r0 + g, rb = r0 + g + 8;
#pragma unroll
            for (int nb = 0; nb < 16; nb++) {
                const int cb = nb * 8 + t * 2;
                if (cb > ra)     s[nb][0] = -1e30f;
                if (cb + 1 > ra) s[nb][1] = -1e30f;
                if (cb > rb)     s[nb][2] = -1e30f;
                if (cb + 1 > rb) s[nb][3] = -1e30f;
            }
        }

        // ---- online softmax in exp2 domain (rows g / g+8) ----
        float mx0 = -INFINITY, mx1 = -INFINITY;
#pragma unroll
        for (int nb = 0; nb < 16; nb++) {
            mx0 = fmaxf(mx0, fmaxf(s[nb][0], s[nb][1]));
            mx1 = fmaxf(mx1, fmaxf(s[nb][2], s[nb][3]));
        }
        mx0 = fmaxf(mx0, __shfl_xor_sync(0xffffffffu, mx0, 1));
        mx0 = fmaxf(mx0, __shfl_xor_sync(0xffffffffu, mx0, 2));
        mx1 = fmaxf(mx1, __shfl_xor_sync(0xffffffffu, mx1, 1));
        mx1 = fmaxf(mx1, __shfl_xor_sync(0xffffffffu, mx1, 2));
        const float mn0 = fmaxf(m0r, mx0);
        const float mn1 = fmaxf(m1r, mx1);
        const float c0 = ex2f(m0r - mn0);
        const float c1 = ex2f(m1r - mn1);
        m0r = mn0; m1r = mn1;
#pragma unroll
        for (int nb = 0; nb < 16; nb++) {
            s[nb][0] = ex2f(s[nb][0] - mn0);
            s[nb][1] = ex2f(s[nb][1] - mn0);
            s[nb][2] = ex2f(s[nb][2] - mn1);
            s[nb][3] = ex2f(s[nb][3] - mn1);
        }
        // rescale O and the normalizer block together
#pragma unroll
        for (int nb = 0; nb < 9; nb++) {
            o[nb][0] *= c0; o[nb][1] *= c0;
            o[nb][2] *= c1; o[nb][3] *= c1;
        }

        // ---- O += P @ V : P fp16 single, V fp16 hi/lo (2-term) + ones col ----
#pragma unroll
        for (int kk = 0; kk < 8; kk++) {
            uint32_t pf[4];
            pf[0] = packhf(s[2 * kk][0], s[2 * kk][1]);
            pf[1] = packhf(s[2 * kk][2], s[2 * kk][3]);
            pf[2] = packhf(s[2 * kk + 1][0], s[2 * kk + 1][1]);
            pf[3] = packhf(s[2 * kk + 1][2], s[2 * kk + 1][3]);
#pragma unroll
            for (int nb = 0; nb < 8; nb += 2) {
                uint32_t vh4[4], vl4[4];
                const uint32_t so = sw_off(kk * 16 + v_row, nb + v_chs);
                ldsm_x4_t(vh4, uVh + so);
                ldsm_x4_t(vl4, uVl + so);
                mma_f16(o[nb], pf, vh4);
                mma_f16(o[nb], pf, vl4);
                mma_f16(o[nb + 1], pf, vh4 + 2);
                mma_f16(o[nb + 1], pf, vl4 + 2);
            }
            mma_f16(o[8], pf, ones2);   // row sums of P -> normalizer
        }
    }

    // ---- normalize and write y (bf16 hi/lo split) ----
    const float inv0 = 1.0f / o[8][0];
    const float inv1 = 1.0f / o[8][2];
    const int row0 = qb * 128 + r0 + g;
    const int row1 = row0 + 8;
#pragma unroll
    for (int nb = 0; nb < 8; nb++) {
        const int col = h * HDIM + nb * 8 + t * 2;
        float a0 = o[nb][0] * inv0, a1 = o[nb][1] * inv0;
        float b0 = o[nb][2] * inv1, b1 = o[nb][3] * inv1;
        uint32_t h0 = packbf(a0, a1);
        uint32_t l0 = packbf(a0 - lo_f(h0), a1 - hi_f(h0));
        uint32_t h1 = packbf(b0, b1);
        uint32_t l1 = packbf(b0 - lo_f(h1), b1 - hi_f(h1));
        *reinterpret_cast<uint32_t*>(yh + (size_t)row0 * C_DIM + col) = h0;
        *reinterpret_cast<uint32_t*>(yl + (size_t)row0 * C_DIM + col) = l0;
        *reinterpret_cast<uint32_t*>(yh + (size_t)row1 * C_DIM + col) = h1;
        *reinterpret_cast<uint32_t*>(yl + (size_t)row1 * C_DIM + col) = l1;
    }
}

// ---------------------------------------------------------------------------
// Launch
// ---------------------------------------------------------------------------
extern "C" void kernel_launch(void* const* d_in, const int* in_sizes, int n_in,
                              void* d_out, int out_size)
{
    (void)in_sizes; (void)n_in; (void)out_size;
    const float* x      = (const float*)d_in[0];
    const float* W_qkv  = (const float*)d_in[2];
    const float* b_qkv  = (const float*)d_in[3];
    const float* W_proj = (const float*)d_in[4];
    const float* b_proj = (const float*)d_in[5];
    float* out = (float*)d_out;

    __nv_bfloat16 *xh, *xl, *qkvh, *qkvl, *yh, *yl, *wqh, *wql, *wph, *wpl;
    cudaGetSymbolAddress((void**)&xh, g_xh);
    cudaGetSymbolAddress((void**)&xl, g_xl);
    cudaGetSymbolAddress((void**)&qkvh, g_qkvh);
    cudaGetSymbolAddress((void**)&qkvl, g_qkvl);
    cudaGetSymbolAddress((void**)&yh, g_yh);
    cudaGetSymbolAddress((void**)&yl, g_yl);
    cudaGetSymbolAddress((void**)&wqh, g_wqh);
    cudaGetSymbolAddress((void**)&wql, g_wql);
    cudaGetSymbolAddress((void**)&wph, g_wph);
    cudaGetSymbolAddress((void**)&wpl, g_wpl);

    cudaFuncSetAttribute(gemm_mma,
                         cudaFuncAttributeMaxDynamicSharedMemorySize, GEMM_SMEM);
    cudaFuncSetAttribute(attn_mma,
                         cudaFuncAttributeMaxDynamicSharedMemorySize, ATT_SMEM);

    // 0) prep: weight transpose+split, input split
    transpose_split<<<dim3(QKV3 / 32, C_DIM / 32), 256>>>(
        W_qkv, wqh, wql, C_DIM, QKV3);
    transpose_split<<<dim3(C_DIM / 32, C_DIM / 32), 256>>>(
        W_proj, wph, wpl, C_DIM, C_DIM);
    split_f32<<<(T_SEQ * C_DIM / 4 + 255) / 256, 256>>>(
        x, xh, xl, T_SEQ * C_DIM / 4);

    // 1) qkv = x @ W_qkv + b_qkv; Q -> log2 domain bf16, K bf16, V fp16 splits
    gemm_mma<<<dim3(QKV3 / 128, T_SEQ / 128), 256, GEMM_SMEM>>>(
        xh, xl, wqh, wql, b_qkv, nullptr, qkvh, qkvl, T_SEQ, QKV3, C_DIM, 1);

    // 2) y = causal_attention(qkv) -> bf16 hi/lo
    attn_mma<<<dim3(T_SEQ / 128, NHEAD), 256, ATT_SMEM>>>(qkvh, qkvl, yh, yl);

    // 3) out = y @ W_proj + b_proj (fp32)
    gemm_mma<<<dim3(C_DIM / 128, T_SEQ / 128), 256, GEMM_SMEM>>>(
        yh, yl, wph, wpl, b_proj, out, nullptr, nullptr, T_SEQ, C_DIM, C_DIM, 0);
}